// round 11
// baseline (speedup 1.0000x reference)
#include <cuda_runtime.h>
#include <cuda_bf16.h>
#include <cstdint>
#include <math.h>

// ---------------- problem constants ----------------
#define T_SEQ 1000
#define BATCH 16
#define M_ROWS (BATCH * T_SEQ)   // 16000
#define NBLK  64                 // blocks per LSTM direction

// ---------------- fp32 scratch ----------------
__device__ float g_h1 [M_ROWS * 1024];
__device__ float g_h2 [(size_t)M_ROWS * 2560];
__device__ float g_xgf[M_ROWS * 1024];
__device__ float g_xgb[M_ROWS * 1024];
__device__ float g_out0[M_ROWS * 512];
__device__ float g_out1[M_ROWS * 512];
__device__ float g_hbuf[2 * 2 * 4096];         // [dir][parity][16*256]
__device__ unsigned g_flagsP[2 * NBLK * 32];   // per-block flag, 128B stride
__device__ unsigned g_go[2 * 8 * 32];          // 8 GO lines per dir, 128B stride

// ---------------- bf16 split scratch ----------------
__device__ __nv_bfloat16 g_xhi [M_ROWS * 80],    g_xlo [M_ROWS * 80];
__device__ __nv_bfloat16 g_w1hi[1024 * 80],      g_w1lo[1024 * 80];
__device__ __nv_bfloat16 g_w2hi[2560 * 1024],    g_w2lo[2560 * 1024];
__device__ __nv_bfloat16 g_h1hi[M_ROWS * 1024],  g_h1lo[M_ROWS * 1024];
__device__ __nv_bfloat16 g_h2hi[(size_t)M_ROWS * 2560], g_h2lo[(size_t)M_ROWS * 2560];
__device__ __nv_bfloat16 g_wl0fhi[1024 * 2560],  g_wl0flo[1024 * 2560];
__device__ __nv_bfloat16 g_wl0bhi[1024 * 2560],  g_wl0blo[1024 * 2560];
__device__ __nv_bfloat16 g_wl1fhi[1024 * 512],   g_wl1flo[1024 * 512];
__device__ __nv_bfloat16 g_wl1bhi[1024 * 512],   g_wl1blo[1024 * 512];
__device__ __nv_bfloat16 g_o0hi[M_ROWS * 512],   g_o0lo[M_ROWS * 512];

// ================= PTX helpers =================
__device__ __forceinline__ uint32_t smem_u32(const void* p) {
    uint32_t a;
    asm("{ .reg .u64 t; cvta.to.shared.u64 t, %1; cvt.u32.u64 %0, t; }" : "=r"(a) : "l"(p));
    return a;
}
__device__ __forceinline__ void cpa16(uint32_t dst, const void* src) {
    asm volatile("cp.async.cg.shared.global [%0], [%1], 16;" :: "r"(dst), "l"(src) : "memory");
}
__device__ __forceinline__ void sts_zero16(uint32_t dst) {
    asm volatile("st.shared.v4.b32 [%0], {%1,%1,%1,%1};" :: "r"(dst), "r"(0u) : "memory");
}
#define CP_COMMIT() asm volatile("cp.async.commit_group;" ::: "memory")
#define CP_WAIT1()  asm volatile("cp.async.wait_group 1;" ::: "memory")
#define CP_WAIT0()  asm volatile("cp.async.wait_group 0;" ::: "memory")

__device__ __forceinline__ void ldsm4(uint32_t addr, uint32_t& r0, uint32_t& r1,
                                      uint32_t& r2, uint32_t& r3) {
    asm volatile("ldmatrix.sync.aligned.m8n8.x4.shared.b16 {%0,%1,%2,%3}, [%4];"
                 : "=r"(r0), "=r"(r1), "=r"(r2), "=r"(r3) : "r"(addr));
}
__device__ __forceinline__ void mma_bf16(float* d, const uint32_t* a, const uint32_t* b) {
    asm volatile(
        "mma.sync.aligned.m16n8k16.row.col.f32.bf16.bf16.f32 "
        "{%0,%1,%2,%3}, {%4,%5,%6,%7}, {%8,%9}, {%0,%1,%2,%3};"
        : "+f"(d[0]), "+f"(d[1]), "+f"(d[2]), "+f"(d[3])
        : "r"(a[0]), "r"(a[1]), "r"(a[2]), "r"(a[3]), "r"(b[0]), "r"(b[1]));
}
// morally-strong relaxed atomics for barrier words (cheap: no ordering cost,
// but participate in fence cumulativity chains, unlike weak st.cg/__ldcg)
__device__ __forceinline__ void st_relaxed_gpu(unsigned* p, unsigned v) {
    asm volatile("st.relaxed.gpu.global.u32 [%0], %1;" :: "l"(p), "r"(v) : "memory");
}
__device__ __forceinline__ unsigned ld_relaxed_gpu(const unsigned* p) {
    unsigned v;
    asm volatile("ld.relaxed.gpu.global.u32 %0, [%1];" : "=r"(v) : "l"(p) : "memory");
    return v;
}

// ---------------- fp32 -> bf16 hi/lo split kernel ----------------
__global__ void conv_split_kernel(const float* __restrict__ src,
                                  __nv_bfloat16* __restrict__ hi,
                                  __nv_bfloat16* __restrict__ lo, int n)
{
    int i = blockIdx.x * blockDim.x + threadIdx.x;
    if (i < n) {
        float v = src[i];
        __nv_bfloat16 h = __float2bfloat16_rn(v);
        hi[i] = h;
        lo[i] = __float2bfloat16_rn(v - __bfloat162float(h));
    }
}

// ================= tensor-core bf16x3 GEMM (unchanged, round-8 proven) ======
#define ROWB   80
#define TILEB  (128 * ROWB)
#define STAGEB (4 * TILEB)
#define GEMM_SMEM_BYTES (1024 + 2 * STAGEB)

__global__ __launch_bounds__(256, 2)
void tc_gemm(const __nv_bfloat16* __restrict__ Ahi, const __nv_bfloat16* __restrict__ Alo,
             const __nv_bfloat16* __restrict__ Bhi, const __nv_bfloat16* __restrict__ Blo,
             const float* __restrict__ bias1, const float* __restrict__ bias2,
             float* __restrict__ C,
             __nv_bfloat16* __restrict__ Chi, __nv_bfloat16* __restrict__ Clo,
             int M, int N, int K, int relu)
{
    extern __shared__ __align__(1024) char smem[];
    const int tid = threadIdx.x;
    const int wid = tid >> 5;
    const int lid = tid & 31;
    const int wm  = wid & 1;
    const int wn  = wid >> 1;
    const uint32_t sbase = smem_u32(smem);
    float* bsm = (float*)(smem);
    const uint32_t tiles = sbase + 1024;

    const int rowBase = blockIdx.y * 128;
    const int colBase = blockIdx.x * 128;

    if (tid < 128) bsm[tid] = bias1[colBase + tid] + (bias2 ? bias2[colBase + tid] : 0.f);

    float acc[4][4][4];
    #pragma unroll
    for (int i = 0; i < 4; i++)
        #pragma unroll
        for (int j = 0; j < 4; j++)
            #pragma unroll
            for (int q = 0; q < 4; q++) acc[i][j][q] = 0.f;

    const int NC = (K + 31) / 32;

    auto load_chunk = [&](int stage, int k0) {
        uint32_t base = tiles + stage * STAGEB;
        const int r  = tid >> 2;
        const int gc = tid & 3;
        const int k  = k0 + (gc << 3);
        #pragma unroll
        for (int i = 0; i < 8; i++) {
            const int part = i >> 1;
            const int row  = ((i & 1) << 6) + r;
            uint32_t dst = base + part * TILEB + row * ROWB + (gc << 4);
            const __nv_bfloat16* mat =
                (part == 0) ? Ahi : (part == 1) ? Alo : (part == 2) ? Bhi : Blo;
            const int gr = (part < 2) ? rowBase + row : colBase + row;
            if (k < K) cpa16(dst, mat + (size_t)gr * K + k);
            else       sts_zero16(dst);
        }
    };

    load_chunk(0, 0);
    CP_COMMIT();

    for (int c = 0; c < NC; c++) {
        if (c + 1 < NC) { load_chunk((c + 1) & 1, (c + 1) * 32); CP_COMMIT(); CP_WAIT1(); }
        else            { CP_WAIT0(); }
        __syncthreads();

        uint32_t abase = tiles + (c & 1) * STAGEB;
        uint32_t bbase = abase + 2 * TILEB;
        const int lm = lid >> 3;
        const int lr = lid & 7;

        #pragma unroll
        for (int ks = 0; ks < 2; ks++) {
            uint32_t ah[4][4], al[4][4], bh[4][2], bl[4][2];
            #pragma unroll
            for (int mt = 0; mt < 4; mt++) {
                uint32_t r = wm * 64 + mt * 16 + ((lm & 1) << 3) + lr;
                uint32_t addr = abase + r * ROWB + (ks << 5) + ((lm >> 1) << 4);
                ldsm4(addr,         ah[mt][0], ah[mt][1], ah[mt][2], ah[mt][3]);
                ldsm4(addr + TILEB, al[mt][0], al[mt][1], al[mt][2], al[mt][3]);
            }
            #pragma unroll
            for (int bt = 0; bt < 2; bt++) {
                uint32_t r = wn * 32 + bt * 16 + ((lm >> 1) << 3) + lr;
                uint32_t addr = bbase + r * ROWB + (ks << 5) + ((lm & 1) << 4);
                uint32_t t0, t1, t2, t3;
                ldsm4(addr, t0, t1, t2, t3);
                bh[2*bt][0] = t0; bh[2*bt][1] = t1; bh[2*bt+1][0] = t2; bh[2*bt+1][1] = t3;
                ldsm4(addr + TILEB, t0, t1, t2, t3);
                bl[2*bt][0] = t0; bl[2*bt][1] = t1; bl[2*bt+1][0] = t2; bl[2*bt+1][1] = t3;
            }
            #pragma unroll
            for (int mt = 0; mt < 4; mt++)
                #pragma unroll
                for (int nt = 0; nt < 4; nt++) {
                    mma_bf16(acc[mt][nt], ah[mt], bl[nt]);
                    mma_bf16(acc[mt][nt], al[mt], bh[nt]);
                    mma_bf16(acc[mt][nt], ah[mt], bh[nt]);
                }
        }
        __syncthreads();
    }

    const int g  = lid >> 2;
    const int tg = lid & 3;
    #pragma unroll
    for (int mt = 0; mt < 4; mt++) {
        int r0 = rowBase + wm * 64 + mt * 16 + g;
        #pragma unroll
        for (int nt = 0; nt < 4; nt++) {
            int cc = wn * 32 + nt * 8 + 2 * tg;
            float b0 = bsm[cc], b1 = bsm[cc + 1];
            float2 v0 = make_float2(acc[mt][nt][0] + b0, acc[mt][nt][1] + b1);
            float2 v1 = make_float2(acc[mt][nt][2] + b0, acc[mt][nt][3] + b1);
            if (relu) {
                v0.x = fmaxf(v0.x, 0.f); v0.y = fmaxf(v0.y, 0.f);
                v1.x = fmaxf(v1.x, 0.f); v1.y = fmaxf(v1.y, 0.f);
            }
            *(float2*)&C[(size_t)r0 * N + cc + colBase] = v0;
            *(float2*)&C[(size_t)(r0 + 8) * N + cc + colBase] = v1;
            if (Chi) {
                __nv_bfloat162 hh, ll;
                hh.x = __float2bfloat16_rn(v0.x);
                hh.y = __float2bfloat16_rn(v0.y);
                ll.x = __float2bfloat16_rn(v0.x - __bfloat162float(hh.x));
                ll.y = __float2bfloat16_rn(v0.y - __bfloat162float(hh.y));
                *(__nv_bfloat162*)&Chi[(size_t)r0 * N + cc + colBase] = hh;
                *(__nv_bfloat162*)&Clo[(size_t)r0 * N + cc + colBase] = ll;
                hh.x = __float2bfloat16_rn(v1.x);
                hh.y = __float2bfloat16_rn(v1.y);
                ll.x = __float2bfloat16_rn(v1.x - __bfloat162float(hh.x));
                ll.y = __float2bfloat16_rn(v1.y - __bfloat162float(hh.y));
                *(__nv_bfloat162*)&Chi[(size_t)(r0 + 8) * N + cc + colBase] = hh;
                *(__nv_bfloat162*)&Clo[(size_t)(r0 + 8) * N + cc + colBase] = ll;
            }
        }
    }
}

// ---------------- init: zero flags/GO + h double buffers --------------------
__global__ void init_rec_kernel()
{
    int t = blockIdx.x * blockDim.x + threadIdx.x;
    if (t < 2 * NBLK * 32) g_flagsP[t] = 0u;
    if (t < 2 * 8 * 32) g_go[t] = 0u;
    if (t < 2 * 2 * 4096) g_hbuf[t] = 0.f;
}

// ---------------- persistent bidirectional LSTM recurrence -----------------
// Barrier v3: parallel per-block arrival flags -> scanner block -> GO lines,
// with the complete cumulative-fence chain:
//   writer:  st h ; fence ; st.relaxed flag
//   scanner: ld.relaxed flag (all) ; syncthreads ; FENCE ; st.relaxed go
//   waiter:  ld.relaxed go ; syncthreads ; fence ; ld h
// (v2's missing scanner fence was the round-10 corruption.)
__global__ __launch_bounds__(256) void lstm_rec_kernel(
    const float* __restrict__ xg_f, const float* __restrict__ xg_b,
    const float* __restrict__ whh_f, const float* __restrict__ whh_b,
    float* __restrict__ out)
{
    const int dir   = blockIdx.x / NBLK;
    const int blk   = blockIdx.x % NBLK;
    const int jbase = blk * 4;
    const int tid   = threadIdx.x;
    const int b     = tid >> 4;
    const int col   = tid & 15;
    const int gate  = col >> 2;
    const int jl    = col & 3;
    const int xgcol = gate * 256 + jbase + jl;

    const float* xg  = dir ? xg_b  : xg_f;
    const float* whh = dir ? whh_b : whh_f;

    __shared__ float wsm[16][260];
    __shared__ float hsm[16][260];
    __shared__ float gsm[16][16];

    for (int i = tid; i < 16 * 256; i += 256) {
        int c = i >> 8, k = i & 255;
        int g2 = c >> 2, j2 = c & 3;
        wsm[c][k] = whh[(g2 * 256 + jbase + j2) * 256 + k];
    }

    float cst = 0.f;
    const int ub = tid >> 2, uj = tid & 3;
    float* hbuf = g_hbuf + dir * 2 * 4096;
    unsigned* flags = g_flagsP + dir * NBLK * 32;
    unsigned* go    = g_go + dir * 8 * 32;
    __syncthreads();

    // prime first timestep's xg
    float xv = __ldg(&xg[(size_t)(b * T_SEQ + (dir ? T_SEQ - 1 : 0)) * 1024 + xgcol]);

    for (int iter = 0; iter < T_SEQ; iter++) {
        const int par = iter & 1;
        // load h_prev [16,256] from L2 into smem
        {
            const float4* src = (const float4*)(hbuf + par * 4096);
            #pragma unroll
            for (int i = 0; i < 4; i++) {
                int id = tid * 4 + i;
                float4 v = __ldcg(&src[id]);
                int bb = id >> 6;
                int kk = (id & 63) << 2;
                *(float4*)&hsm[bb][kk] = v;
            }
        }
        __syncthreads();

        const int t = dir ? (T_SEQ - 1 - iter) : iter;

        float a0 = 0.f, a1 = 0.f, a2 = 0.f, a3 = 0.f;
        const float4* wr = (const float4*)&wsm[col][0];
        const float4* hr = (const float4*)&hsm[b][0];
        #pragma unroll 8
        for (int k4 = 0; k4 < 64; k4++) {
            float4 w = wr[k4];
            float4 h = hr[k4];
            a0 = fmaf(w.x, h.x, a0);
            a1 = fmaf(w.y, h.y, a1);
            a2 = fmaf(w.z, h.z, a2);
            a3 = fmaf(w.w, h.w, a3);
        }
        gsm[b][col] = (a0 + a1) + (a2 + a3) + xv;
        __syncthreads();

        float hv = 0.f;
        if (tid < 64) {
            float gi = gsm[ub][0  + uj];
            float gf = gsm[ub][4  + uj];
            float gg = gsm[ub][8  + uj];
            float go_ = gsm[ub][12 + uj];
            float si = 1.f / (1.f + expf(-gi));
            float sf = 1.f / (1.f + expf(-gf));
            float tg = tanhf(gg);
            float so = 1.f / (1.f + expf(-go_));
            cst = sf * cst + si * tg;
            hv = so * tanhf(cst);
            hbuf[(par ^ 1) * 4096 + ub * 256 + jbase + uj] = hv;
            __threadfence();   // release: h visible before this block's flag
        }
        __syncthreads();       // all writers fenced before publish

        // arrival: ONE relaxed-atomic store to this block's private flag line
        if (tid == 0) st_relaxed_gpu(&flags[blk * 32], (unsigned)(iter + 1));

        // off-critical-path work while the barrier settles
        if (tid < 64)
            out[(size_t)(ub * T_SEQ + t) * 512 + dir * 256 + jbase + uj] = hv;
        float xv_next = 0.f;
        if (iter + 1 < T_SEQ) {
            int tn = dir ? (T_SEQ - 2 - iter) : (iter + 1);
            xv_next = __ldg(&xg[(size_t)(b * T_SEQ + tn) * 1024 + xgcol]);
        }

        const unsigned target = (unsigned)(iter + 1);
        if (blk == 0) {
            // scanner: thread t watches block t's flag (1 poller per line)
            if (tid < NBLK) {
                while (ld_relaxed_gpu(&flags[tid * 32]) < target) { }
            }
            __syncthreads();
            __threadfence();   // CUMULATIVITY FENCE: order observed h-writes
                               // before the GO release (v2's missing link)
            if (tid < 8) st_relaxed_gpu(&go[tid * 32], target);
        } else {
            if (tid == 0) {
                const unsigned* myGo = &go[(blk >> 3) * 32];
                while (ld_relaxed_gpu(myGo) < target) { }
            }
        }
        __syncthreads();
        __threadfence();       // acquire: order next h loads after observation
        xv = xv_next;
    }
}

// ---------------- final FC: [16000,512] @ [29,512]^T + b -------------------
__global__ __launch_bounds__(256) void fc_kernel(
    const float* __restrict__ A, const float* __restrict__ W,
    const float* __restrict__ bias, float* __restrict__ out)
{
    __shared__ float as[8][512];
    int r0 = blockIdx.x * 8;
    for (int i = threadIdx.x; i < 8 * 512; i += 256)
        as[i >> 9][i & 511] = A[(size_t)(r0 + (i >> 9)) * 512 + (i & 511)];
    __syncthreads();

    int r = threadIdx.x >> 5;
    int c = threadIdx.x & 31;
    if (c < 29) {
        const float* w = W + c * 512;
        float acc = 0.f;
        #pragma unroll 8
        for (int k = 0; k < 512; k++) acc = fmaf(as[r][k], __ldg(&w[k]), acc);
        out[(size_t)(r0 + r) * 29 + c] = acc + bias[c];
    }
}

// ---------------- launch ---------------------------------------------------
extern "C" void kernel_launch(void* const* d_in, const int* in_sizes, int n_in,
                              void* d_out, int out_size)
{
    (void)in_sizes; (void)n_in; (void)out_size;
    const float* x        = (const float*)d_in[0];
    const float* fe_w1    = (const float*)d_in[1];
    const float* fe_b1    = (const float*)d_in[2];
    const float* fe_w2    = (const float*)d_in[3];
    const float* fe_b2    = (const float*)d_in[4];
    const float* w_ih_l0f = (const float*)d_in[5];
    const float* w_hh_l0f = (const float*)d_in[6];
    const float* b_ih_l0f = (const float*)d_in[7];
    const float* b_hh_l0f = (const float*)d_in[8];
    const float* w_ih_l0b = (const float*)d_in[9];
    const float* w_hh_l0b = (const float*)d_in[10];
    const float* b_ih_l0b = (const float*)d_in[11];
    const float* b_hh_l0b = (const float*)d_in[12];
    const float* w_ih_l1f = (const float*)d_in[13];
    const float* w_hh_l1f = (const float*)d_in[14];
    const float* b_ih_l1f = (const float*)d_in[15];
    const float* b_hh_l1f = (const float*)d_in[16];
    const float* w_ih_l1b = (const float*)d_in[17];
    const float* w_hh_l1b = (const float*)d_in[18];
    const float* b_ih_l1b = (const float*)d_in[19];
    const float* b_hh_l1b = (const float*)d_in[20];
    const float* fc_w     = (const float*)d_in[21];
    const float* fc_b     = (const float*)d_in[22];
    float* out = (float*)d_out;

    float *h1, *h2, *xgf, *xgb, *o0, *o1;
    cudaGetSymbolAddress((void**)&h1,  g_h1);
    cudaGetSymbolAddress((void**)&h2,  g_h2);
    cudaGetSymbolAddress((void**)&xgf, g_xgf);
    cudaGetSymbolAddress((void**)&xgb, g_xgb);
    cudaGetSymbolAddress((void**)&o0,  g_out0);
    cudaGetSymbolAddress((void**)&o1,  g_out1);

    __nv_bfloat16 *xhi, *xlo, *w1hi, *w1lo, *w2hi, *w2lo;
    __nv_bfloat16 *h1hi, *h1lo, *h2hi, *h2lo;
    __nv_bfloat16 *wl0fhi, *wl0flo, *wl0bhi, *wl0blo;
    __nv_bfloat16 *wl1fhi, *wl1flo, *wl1bhi, *wl1blo, *o0hi, *o0lo;
    cudaGetSymbolAddress((void**)&xhi,    g_xhi);    cudaGetSymbolAddress((void**)&xlo,    g_xlo);
    cudaGetSymbolAddress((void**)&w1hi,   g_w1hi);   cudaGetSymbolAddress((void**)&w1lo,   g_w1lo);
    cudaGetSymbolAddress((void**)&w2hi,   g_w2hi);   cudaGetSymbolAddress((void**)&w2lo,   g_w2lo);
    cudaGetSymbolAddress((void**)&h1hi,   g_h1hi);   cudaGetSymbolAddress((void**)&h1lo,   g_h1lo);
    cudaGetSymbolAddress((void**)&h2hi,   g_h2hi);   cudaGetSymbolAddress((void**)&h2lo,   g_h2lo);
    cudaGetSymbolAddress((void**)&wl0fhi, g_wl0fhi); cudaGetSymbolAddress((void**)&wl0flo, g_wl0flo);
    cudaGetSymbolAddress((void**)&wl0bhi, g_wl0bhi); cudaGetSymbolAddress((void**)&wl0blo, g_wl0blo);
    cudaGetSymbolAddress((void**)&wl1fhi, g_wl1fhi); cudaGetSymbolAddress((void**)&wl1flo, g_wl1flo);
    cudaGetSymbolAddress((void**)&wl1bhi, g_wl1bhi); cudaGetSymbolAddress((void**)&wl1blo, g_wl1blo);
    cudaGetSymbolAddress((void**)&o0hi,   g_o0hi);   cudaGetSymbolAddress((void**)&o0lo,   g_o0lo);

    cudaFuncSetAttribute(tc_gemm, cudaFuncAttributeMaxDynamicSharedMemorySize, GEMM_SMEM_BYTES);

    #define CONV(src, hi, lo, n) conv_split_kernel<<<((n) + 255) / 256, 256>>>(src, hi, lo, n)
    CONV(x, xhi, xlo, M_ROWS * 80);
    CONV(fe_w1, w1hi, w1lo, 1024 * 80);
    CONV(fe_w2, w2hi, w2lo, 2560 * 1024);
    CONV(w_ih_l0f, wl0fhi, wl0flo, 1024 * 2560);
    CONV(w_ih_l0b, wl0bhi, wl0blo, 1024 * 2560);
    CONV(w_ih_l1f, wl1fhi, wl1flo, 1024 * 512);
    CONV(w_ih_l1b, wl1bhi, wl1blo, 1024 * 512);

    // feature extractor
    tc_gemm<<<dim3(8,  M_ROWS / 128), 256, GEMM_SMEM_BYTES>>>(
        xhi, xlo, w1hi, w1lo, fe_b1, nullptr, h1, h1hi, h1lo, M_ROWS, 1024, 80, 1);
    tc_gemm<<<dim3(20, M_ROWS / 128), 256, GEMM_SMEM_BYTES>>>(
        h1hi, h1lo, w2hi, w2lo, fe_b2, nullptr, h2, h2hi, h2lo, M_ROWS, 2560, 1024, 1);

    // layer 0: gate precompute + recurrence
    tc_gemm<<<dim3(8, M_ROWS / 128), 256, GEMM_SMEM_BYTES>>>(
        h2hi, h2lo, wl0fhi, wl0flo, b_ih_l0f, b_hh_l0f, xgf, nullptr, nullptr, M_ROWS, 1024, 2560, 0);
    tc_gemm<<<dim3(8, M_ROWS / 128), 256, GEMM_SMEM_BYTES>>>(
        h2hi, h2lo, wl0bhi, wl0blo, b_ih_l0b, b_hh_l0b, xgb, nullptr, nullptr, M_ROWS, 1024, 2560, 0);
    init_rec_kernel<<<64, 256>>>();
    lstm_rec_kernel<<<2 * NBLK, 256>>>(xgf, xgb, w_hh_l0f, w_hh_l0b, o0);

    // layer 1
    CONV(o0, o0hi, o0lo, M_ROWS * 512);
    tc_gemm<<<dim3(8, M_ROWS / 128), 256, GEMM_SMEM_BYTES>>>(
        o0hi, o0lo, wl1fhi, wl1flo, b_ih_l1f, b_hh_l1f, xgf, nullptr, nullptr, M_ROWS, 1024, 512, 0);
    tc_gemm<<<dim3(8, M_ROWS / 128), 256, GEMM_SMEM_BYTES>>>(
        o0hi, o0lo, wl1bhi, wl1blo, b_ih_l1b, b_hh_l1b, xgb, nullptr, nullptr, M_ROWS, 1024, 512, 0);
    init_rec_kernel<<<64, 256>>>();
    lstm_rec_kernel<<<2 * NBLK, 256>>>(xgf, xgb, w_hh_l1f, w_hh_l1b, o1);

    // classifier
    fc_kernel<<<M_ROWS / 8, 256>>>(o1, fc_w, fc_b, out);
    #undef CONV
}

// round 12
// speedup vs baseline: 1.1088x; 1.1088x over previous
#include <cuda_runtime.h>
#include <cuda_bf16.h>
#include <cstdint>
#include <math.h>

// ---------------- problem constants ----------------
#define T_SEQ 1000
#define BATCH 16
#define M_ROWS (BATCH * T_SEQ)   // 16000
#define NBLK  64                 // blocks per LSTM direction

// ---------------- fp32 scratch ----------------
__device__ float g_h1 [M_ROWS * 1024];
__device__ float g_h2 [(size_t)M_ROWS * 2560];
__device__ float g_xgf[M_ROWS * 1024];
__device__ float g_xgb[M_ROWS * 1024];
__device__ float g_out0[M_ROWS * 512];
__device__ float g_out1[M_ROWS * 512];
__device__ float g_hbuf[2 * 2 * 4096];   // [dir][parity][16*256]
__device__ unsigned g_barctr[2];

// ---------------- bf16 split scratch ----------------
__device__ __nv_bfloat16 g_xhi [M_ROWS * 80],    g_xlo [M_ROWS * 80];
__device__ __nv_bfloat16 g_w1hi[1024 * 80],      g_w1lo[1024 * 80];
__device__ __nv_bfloat16 g_w2hi[2560 * 1024],    g_w2lo[2560 * 1024];
__device__ __nv_bfloat16 g_h1hi[M_ROWS * 1024],  g_h1lo[M_ROWS * 1024];
__device__ __nv_bfloat16 g_h2hi[(size_t)M_ROWS * 2560], g_h2lo[(size_t)M_ROWS * 2560];
__device__ __nv_bfloat16 g_wl0fhi[1024 * 2560],  g_wl0flo[1024 * 2560];
__device__ __nv_bfloat16 g_wl0bhi[1024 * 2560],  g_wl0blo[1024 * 2560];
__device__ __nv_bfloat16 g_wl1fhi[1024 * 512],   g_wl1flo[1024 * 512];
__device__ __nv_bfloat16 g_wl1bhi[1024 * 512],   g_wl1blo[1024 * 512];
__device__ __nv_bfloat16 g_o0hi[M_ROWS * 512],   g_o0lo[M_ROWS * 512];

// ================= PTX helpers =================
__device__ __forceinline__ uint32_t smem_u32(const void* p) {
    uint32_t a;
    asm("{ .reg .u64 t; cvta.to.shared.u64 t, %1; cvt.u32.u64 %0, t; }" : "=r"(a) : "l"(p));
    return a;
}
__device__ __forceinline__ void cpa16(uint32_t dst, const void* src) {
    asm volatile("cp.async.cg.shared.global [%0], [%1], 16;" :: "r"(dst), "l"(src) : "memory");
}
__device__ __forceinline__ void sts_zero16(uint32_t dst) {
    asm volatile("st.shared.v4.b32 [%0], {%1,%1,%1,%1};" :: "r"(dst), "r"(0u) : "memory");
}
#define CP_COMMIT() asm volatile("cp.async.commit_group;" ::: "memory")
#define CP_WAIT1()  asm volatile("cp.async.wait_group 1;" ::: "memory")
#define CP_WAIT0()  asm volatile("cp.async.wait_group 0;" ::: "memory")

__device__ __forceinline__ void ldsm4(uint32_t addr, uint32_t& r0, uint32_t& r1,
                                      uint32_t& r2, uint32_t& r3) {
    asm volatile("ldmatrix.sync.aligned.m8n8.x4.shared.b16 {%0,%1,%2,%3}, [%4];"
                 : "=r"(r0), "=r"(r1), "=r"(r2), "=r"(r3) : "r"(addr));
}
__device__ __forceinline__ void mma_bf16(float* d, const uint32_t* a, const uint32_t* b) {
    asm volatile(
        "mma.sync.aligned.m16n8k16.row.col.f32.bf16.bf16.f32 "
        "{%0,%1,%2,%3}, {%4,%5,%6,%7}, {%8,%9}, {%0,%1,%2,%3};"
        : "+f"(d[0]), "+f"(d[1]), "+f"(d[2]), "+f"(d[3])
        : "r"(a[0]), "r"(a[1]), "r"(a[2]), "r"(a[3]), "r"(b[0]), "r"(b[1]));
}

// ---------------- fp32 -> bf16 hi/lo split kernel ----------------
__global__ void conv_split_kernel(const float* __restrict__ src,
                                  __nv_bfloat16* __restrict__ hi,
                                  __nv_bfloat16* __restrict__ lo, int n)
{
    int i = blockIdx.x * blockDim.x + threadIdx.x;
    if (i < n) {
        float v = src[i];
        __nv_bfloat16 h = __float2bfloat16_rn(v);
        hi[i] = h;
        lo[i] = __float2bfloat16_rn(v - __bfloat162float(h));
    }
}

// ================= tensor-core bf16x3 GEMM (round-8 proven) =================
#define ROWB   80
#define TILEB  (128 * ROWB)
#define STAGEB (4 * TILEB)
#define GEMM_SMEM_BYTES (1024 + 2 * STAGEB)

__global__ __launch_bounds__(256, 2)
void tc_gemm(const __nv_bfloat16* __restrict__ Ahi, const __nv_bfloat16* __restrict__ Alo,
             const __nv_bfloat16* __restrict__ Bhi, const __nv_bfloat16* __restrict__ Blo,
             const float* __restrict__ bias1, const float* __restrict__ bias2,
             float* __restrict__ C,
             __nv_bfloat16* __restrict__ Chi, __nv_bfloat16* __restrict__ Clo,
             int M, int N, int K, int relu)
{
    extern __shared__ __align__(1024) char smem[];
    const int tid = threadIdx.x;
    const int wid = tid >> 5;
    const int lid = tid & 31;
    const int wm  = wid & 1;
    const int wn  = wid >> 1;
    const uint32_t sbase = smem_u32(smem);
    float* bsm = (float*)(smem);
    const uint32_t tiles = sbase + 1024;

    const int rowBase = blockIdx.y * 128;
    const int colBase = blockIdx.x * 128;

    if (tid < 128) bsm[tid] = bias1[colBase + tid] + (bias2 ? bias2[colBase + tid] : 0.f);

    float acc[4][4][4];
    #pragma unroll
    for (int i = 0; i < 4; i++)
        #pragma unroll
        for (int j = 0; j < 4; j++)
            #pragma unroll
            for (int q = 0; q < 4; q++) acc[i][j][q] = 0.f;

    const int NC = (K + 31) / 32;

    auto load_chunk = [&](int stage, int k0) {
        uint32_t base = tiles + stage * STAGEB;
        const int r  = tid >> 2;
        const int gc = tid & 3;
        const int k  = k0 + (gc << 3);
        #pragma unroll
        for (int i = 0; i < 8; i++) {
            const int part = i >> 1;
            const int row  = ((i & 1) << 6) + r;
            uint32_t dst = base + part * TILEB + row * ROWB + (gc << 4);
            const __nv_bfloat16* mat =
                (part == 0) ? Ahi : (part == 1) ? Alo : (part == 2) ? Bhi : Blo;
            const int gr = (part < 2) ? rowBase + row : colBase + row;
            if (k < K) cpa16(dst, mat + (size_t)gr * K + k);
            else       sts_zero16(dst);
        }
    };

    load_chunk(0, 0);
    CP_COMMIT();

    for (int c = 0; c < NC; c++) {
        if (c + 1 < NC) { load_chunk((c + 1) & 1, (c + 1) * 32); CP_COMMIT(); CP_WAIT1(); }
        else            { CP_WAIT0(); }
        __syncthreads();

        uint32_t abase = tiles + (c & 1) * STAGEB;
        uint32_t bbase = abase + 2 * TILEB;
        const int lm = lid >> 3;
        const int lr = lid & 7;

        #pragma unroll
        for (int ks = 0; ks < 2; ks++) {
            uint32_t ah[4][4], al[4][4], bh[4][2], bl[4][2];
            #pragma unroll
            for (int mt = 0; mt < 4; mt++) {
                uint32_t r = wm * 64 + mt * 16 + ((lm & 1) << 3) + lr;
                uint32_t addr = abase + r * ROWB + (ks << 5) + ((lm >> 1) << 4);
                ldsm4(addr,         ah[mt][0], ah[mt][1], ah[mt][2], ah[mt][3]);
                ldsm4(addr + TILEB, al[mt][0], al[mt][1], al[mt][2], al[mt][3]);
            }
            #pragma unroll
            for (int bt = 0; bt < 2; bt++) {
                uint32_t r = wn * 32 + bt * 16 + ((lm >> 1) << 3) + lr;
                uint32_t addr = bbase + r * ROWB + (ks << 5) + ((lm & 1) << 4);
                uint32_t t0, t1, t2, t3;
                ldsm4(addr, t0, t1, t2, t3);
                bh[2*bt][0] = t0; bh[2*bt][1] = t1; bh[2*bt+1][0] = t2; bh[2*bt+1][1] = t3;
                ldsm4(addr + TILEB, t0, t1, t2, t3);
                bl[2*bt][0] = t0; bl[2*bt][1] = t1; bl[2*bt+1][0] = t2; bl[2*bt+1][1] = t3;
            }
            #pragma unroll
            for (int mt = 0; mt < 4; mt++)
                #pragma unroll
                for (int nt = 0; nt < 4; nt++) {
                    mma_bf16(acc[mt][nt], ah[mt], bl[nt]);
                    mma_bf16(acc[mt][nt], al[mt], bh[nt]);
                    mma_bf16(acc[mt][nt], ah[mt], bh[nt]);
                }
        }
        __syncthreads();
    }

    const int g  = lid >> 2;
    const int tg = lid & 3;
    #pragma unroll
    for (int mt = 0; mt < 4; mt++) {
        int r0 = rowBase + wm * 64 + mt * 16 + g;
        #pragma unroll
        for (int nt = 0; nt < 4; nt++) {
            int cc = wn * 32 + nt * 8 + 2 * tg;
            float b0 = bsm[cc], b1 = bsm[cc + 1];
            float2 v0 = make_float2(acc[mt][nt][0] + b0, acc[mt][nt][1] + b1);
            float2 v1 = make_float2(acc[mt][nt][2] + b0, acc[mt][nt][3] + b1);
            if (relu) {
                v0.x = fmaxf(v0.x, 0.f); v0.y = fmaxf(v0.y, 0.f);
                v1.x = fmaxf(v1.x, 0.f); v1.y = fmaxf(v1.y, 0.f);
            }
            *(float2*)&C[(size_t)r0 * N + cc + colBase] = v0;
            *(float2*)&C[(size_t)(r0 + 8) * N + cc + colBase] = v1;
            if (Chi) {
                __nv_bfloat162 hh, ll;
                hh.x = __float2bfloat16_rn(v0.x);
                hh.y = __float2bfloat16_rn(v0.y);
                ll.x = __float2bfloat16_rn(v0.x - __bfloat162float(hh.x));
                ll.y = __float2bfloat16_rn(v0.y - __bfloat162float(hh.y));
                *(__nv_bfloat162*)&Chi[(size_t)r0 * N + cc + colBase] = hh;
                *(__nv_bfloat162*)&Clo[(size_t)r0 * N + cc + colBase] = ll;
                hh.x = __float2bfloat16_rn(v1.x);
                hh.y = __float2bfloat16_rn(v1.y);
                ll.x = __float2bfloat16_rn(v1.x - __bfloat162float(hh.x));
                ll.y = __float2bfloat16_rn(v1.y - __bfloat162float(hh.y));
                *(__nv_bfloat162*)&Chi[(size_t)(r0 + 8) * N + cc + colBase] = hh;
                *(__nv_bfloat162*)&Clo[(size_t)(r0 + 8) * N + cc + colBase] = ll;
            }
        }
    }
}

// ---------------- init: zero barrier counters + h double buffers -----------
__global__ void init_rec_kernel()
{
    int t = blockIdx.x * blockDim.x + threadIdx.x;
    if (t < 2) g_barctr[t] = 0u;
    if (t < 2 * 2 * 4096) g_hbuf[t] = 0.f;
}

// ---------------- persistent bidirectional LSTM recurrence -----------------
// R8 barrier protocol EXACTLY (atomic counter + volatile poll + nanosleep,
// threadfence release/acquire) + two critical-path removals proven in the
// R11 passing kernel: xg prefetched during the previous barrier wait, and
// the out[] store deferred until after the arrival atomic.
__global__ __launch_bounds__(256) void lstm_rec_kernel(
    const float* __restrict__ xg_f, const float* __restrict__ xg_b,
    const float* __restrict__ whh_f, const float* __restrict__ whh_b,
    float* __restrict__ out)
{
    const int dir   = blockIdx.x / NBLK;
    const int blk   = blockIdx.x % NBLK;
    const int jbase = blk * 4;
    const int tid   = threadIdx.x;
    const int b     = tid >> 4;
    const int col   = tid & 15;
    const int gate  = col >> 2;
    const int jl    = col & 3;
    const int xgcol = gate * 256 + jbase + jl;

    const float* xg  = dir ? xg_b  : xg_f;
    const float* whh = dir ? whh_b : whh_f;

    __shared__ float wsm[16][260];
    __shared__ float hsm[16][260];
    __shared__ float gsm[16][16];

    for (int i = tid; i < 16 * 256; i += 256) {
        int c = i >> 8, k = i & 255;
        int g2 = c >> 2, j2 = c & 3;
        wsm[c][k] = whh[(g2 * 256 + jbase + j2) * 256 + k];
    }

    float cst = 0.f;
    const int ub = tid >> 2, uj = tid & 3;
    float* hbuf = g_hbuf + dir * 2 * 4096;
    unsigned* ctr = &g_barctr[dir];
    __syncthreads();

    // prime first timestep's xg
    float xv = __ldg(&xg[(size_t)(b * T_SEQ + (dir ? T_SEQ - 1 : 0)) * 1024 + xgcol]);

    for (int iter = 0; iter < T_SEQ; iter++) {
        const int par = iter & 1;
        {
            const float4* src = (const float4*)(hbuf + par * 4096);
            #pragma unroll
            for (int i = 0; i < 4; i++) {
                int id = tid * 4 + i;
                float4 v = __ldcg(&src[id]);
                int bb = id >> 6;
                int kk = (id & 63) << 2;
                *(float4*)&hsm[bb][kk] = v;
            }
        }
        __syncthreads();

        const int t = dir ? (T_SEQ - 1 - iter) : iter;

        float a0 = 0.f, a1 = 0.f, a2 = 0.f, a3 = 0.f;
        const float4* wr = (const float4*)&wsm[col][0];
        const float4* hr = (const float4*)&hsm[b][0];
        #pragma unroll 8
        for (int k4 = 0; k4 < 64; k4++) {
            float4 w = wr[k4];
            float4 h = hr[k4];
            a0 = fmaf(w.x, h.x, a0);
            a1 = fmaf(w.y, h.y, a1);
            a2 = fmaf(w.z, h.z, a2);
            a3 = fmaf(w.w, h.w, a3);
        }
        gsm[b][col] = (a0 + a1) + (a2 + a3) + xv;
        __syncthreads();

        float hv = 0.f;
        if (tid < 64) {
            float gi = gsm[ub][0  + uj];
            float gf = gsm[ub][4  + uj];
            float gg = gsm[ub][8  + uj];
            float go = gsm[ub][12 + uj];
            float si = 1.f / (1.f + expf(-gi));
            float sf = 1.f / (1.f + expf(-gf));
            float tg = tanhf(gg);
            float so = 1.f / (1.f + expf(-go));
            cst = sf * cst + si * tg;
            hv = so * tanhf(cst);
            hbuf[(par ^ 1) * 4096 + ub * 256 + jbase + uj] = hv;
            __threadfence();   // release: h visible before the arrival atomic
        }
        __syncthreads();       // all writers fenced before arrival

        if (tid == 0) atomicAdd(ctr, 1u);

        // off-critical-path while the barrier fills:
        if (tid < 64)          // deferred output store (unique addrs, unfenced)
            out[(size_t)(ub * T_SEQ + t) * 512 + dir * 256 + jbase + uj] = hv;
        float xv_next = 0.f;   // prefetch next timestep's xg (DRAM latency hidden)
        if (iter + 1 < T_SEQ) {
            int tn = dir ? (T_SEQ - 2 - iter) : (iter + 1);
            xv_next = __ldg(&xg[(size_t)(b * T_SEQ + tn) * 1024 + xgcol]);
        }

        if (tid == 0) {
            unsigned target = (unsigned)(iter + 1) * NBLK;
            while (*((volatile unsigned*)ctr) < target) { __nanosleep(32); }
        }
        __syncthreads();
        __threadfence();       // acquire: order next h loads after observation
        xv = xv_next;
    }
}

// ---------------- final FC: [16000,512] @ [29,512]^T + b -------------------
__global__ __launch_bounds__(256) void fc_kernel(
    const float* __restrict__ A, const float* __restrict__ W,
    const float* __restrict__ bias, float* __restrict__ out)
{
    __shared__ float as[8][512];
    int r0 = blockIdx.x * 8;
    for (int i = threadIdx.x; i < 8 * 512; i += 256)
        as[i >> 9][i & 511] = A[(size_t)(r0 + (i >> 9)) * 512 + (i & 511)];
    __syncthreads();

    int r = threadIdx.x >> 5;
    int c = threadIdx.x & 31;
    if (c < 29) {
        const float* w = W + c * 512;
        float acc = 0.f;
        #pragma unroll 8
        for (int k = 0; k < 512; k++) acc = fmaf(as[r][k], __ldg(&w[k]), acc);
        out[(size_t)(r0 + r) * 29 + c] = acc + bias[c];
    }
}

// ---------------- launch ---------------------------------------------------
extern "C" void kernel_launch(void* const* d_in, const int* in_sizes, int n_in,
                              void* d_out, int out_size)
{
    (void)in_sizes; (void)n_in; (void)out_size;
    const float* x        = (const float*)d_in[0];
    const float* fe_w1    = (const float*)d_in[1];
    const float* fe_b1    = (const float*)d_in[2];
    const float* fe_w2    = (const float*)d_in[3];
    const float* fe_b2    = (const float*)d_in[4];
    const float* w_ih_l0f = (const float*)d_in[5];
    const float* w_hh_l0f = (const float*)d_in[6];
    const float* b_ih_l0f = (const float*)d_in[7];
    const float* b_hh_l0f = (const float*)d_in[8];
    const float* w_ih_l0b = (const float*)d_in[9];
    const float* w_hh_l0b = (const float*)d_in[10];
    const float* b_ih_l0b = (const float*)d_in[11];
    const float* b_hh_l0b = (const float*)d_in[12];
    const float* w_ih_l1f = (const float*)d_in[13];
    const float* w_hh_l1f = (const float*)d_in[14];
    const float* b_ih_l1f = (const float*)d_in[15];
    const float* b_hh_l1f = (const float*)d_in[16];
    const float* w_ih_l1b = (const float*)d_in[17];
    const float* w_hh_l1b = (const float*)d_in[18];
    const float* b_ih_l1b = (const float*)d_in[19];
    const float* b_hh_l1b = (const float*)d_in[20];
    const float* fc_w     = (const float*)d_in[21];
    const float* fc_b     = (const float*)d_in[22];
    float* out = (float*)d_out;

    float *h1, *h2, *xgf, *xgb, *o0, *o1;
    cudaGetSymbolAddress((void**)&h1,  g_h1);
    cudaGetSymbolAddress((void**)&h2,  g_h2);
    cudaGetSymbolAddress((void**)&xgf, g_xgf);
    cudaGetSymbolAddress((void**)&xgb, g_xgb);
    cudaGetSymbolAddress((void**)&o0,  g_out0);
    cudaGetSymbolAddress((void**)&o1,  g_out1);

    __nv_bfloat16 *xhi, *xlo, *w1hi, *w1lo, *w2hi, *w2lo;
    __nv_bfloat16 *h1hi, *h1lo, *h2hi, *h2lo;
    __nv_bfloat16 *wl0fhi, *wl0flo, *wl0bhi, *wl0blo;
    __nv_bfloat16 *wl1fhi, *wl1flo, *wl1bhi, *wl1blo, *o0hi, *o0lo;
    cudaGetSymbolAddress((void**)&xhi,    g_xhi);    cudaGetSymbolAddress((void**)&xlo,    g_xlo);
    cudaGetSymbolAddress((void**)&w1hi,   g_w1hi);   cudaGetSymbolAddress((void**)&w1lo,   g_w1lo);
    cudaGetSymbolAddress((void**)&w2hi,   g_w2hi);   cudaGetSymbolAddress((void**)&w2lo,   g_w2lo);
    cudaGetSymbolAddress((void**)&h1hi,   g_h1hi);   cudaGetSymbolAddress((void**)&h1lo,   g_h1lo);
    cudaGetSymbolAddress((void**)&h2hi,   g_h2hi);   cudaGetSymbolAddress((void**)&h2lo,   g_h2lo);
    cudaGetSymbolAddress((void**)&wl0fhi, g_wl0fhi); cudaGetSymbolAddress((void**)&wl0flo, g_wl0flo);
    cudaGetSymbolAddress((void**)&wl0bhi, g_wl0bhi); cudaGetSymbolAddress((void**)&wl0blo, g_wl0blo);
    cudaGetSymbolAddress((void**)&wl1fhi, g_wl1fhi); cudaGetSymbolAddress((void**)&wl1flo, g_wl1flo);
    cudaGetSymbolAddress((void**)&wl1bhi, g_wl1bhi); cudaGetSymbolAddress((void**)&wl1blo, g_wl1blo);
    cudaGetSymbolAddress((void**)&o0hi,   g_o0hi);   cudaGetSymbolAddress((void**)&o0lo,   g_o0lo);

    cudaFuncSetAttribute(tc_gemm, cudaFuncAttributeMaxDynamicSharedMemorySize, GEMM_SMEM_BYTES);

    #define CONV(src, hi, lo, n) conv_split_kernel<<<((n) + 255) / 256, 256>>>(src, hi, lo, n)
    CONV(x, xhi, xlo, M_ROWS * 80);
    CONV(fe_w1, w1hi, w1lo, 1024 * 80);
    CONV(fe_w2, w2hi, w2lo, 2560 * 1024);
    CONV(w_ih_l0f, wl0fhi, wl0flo, 1024 * 2560);
    CONV(w_ih_l0b, wl0bhi, wl0blo, 1024 * 2560);
    CONV(w_ih_l1f, wl1fhi, wl1flo, 1024 * 512);
    CONV(w_ih_l1b, wl1bhi, wl1blo, 1024 * 512);

    // feature extractor
    tc_gemm<<<dim3(8,  M_ROWS / 128), 256, GEMM_SMEM_BYTES>>>(
        xhi, xlo, w1hi, w1lo, fe_b1, nullptr, h1, h1hi, h1lo, M_ROWS, 1024, 80, 1);
    tc_gemm<<<dim3(20, M_ROWS / 128), 256, GEMM_SMEM_BYTES>>>(
        h1hi, h1lo, w2hi, w2lo, fe_b2, nullptr, h2, h2hi, h2lo, M_ROWS, 2560, 1024, 1);

    // layer 0: gate precompute + recurrence
    tc_gemm<<<dim3(8, M_ROWS / 128), 256, GEMM_SMEM_BYTES>>>(
        h2hi, h2lo, wl0fhi, wl0flo, b_ih_l0f, b_hh_l0f, xgf, nullptr, nullptr, M_ROWS, 1024, 2560, 0);
    tc_gemm<<<dim3(8, M_ROWS / 128), 256, GEMM_SMEM_BYTES>>>(
        h2hi, h2lo, wl0bhi, wl0blo, b_ih_l0b, b_hh_l0b, xgb, nullptr, nullptr, M_ROWS, 1024, 2560, 0);
    init_rec_kernel<<<64, 256>>>();
    lstm_rec_kernel<<<2 * NBLK, 256>>>(xgf, xgb, w_hh_l0f, w_hh_l0b, o0);

    // layer 1
    CONV(o0, o0hi, o0lo, M_ROWS * 512);
    tc_gemm<<<dim3(8, M_ROWS / 128), 256, GEMM_SMEM_BYTES>>>(
        o0hi, o0lo, wl1fhi, wl1flo, b_ih_l1f, b_hh_l1f, xgf, nullptr, nullptr, M_ROWS, 1024, 512, 0);
    tc_gemm<<<dim3(8, M_ROWS / 128), 256, GEMM_SMEM_BYTES>>>(
        o0hi, o0lo, wl1bhi, wl1blo, b_ih_l1b, b_hh_l1b, xgb, nullptr, nullptr, M_ROWS, 1024, 512, 0);
    init_rec_kernel<<<64, 256>>>();
    lstm_rec_kernel<<<2 * NBLK, 256>>>(xgf, xgb, w_hh_l1f, w_hh_l1b, o1);

    // classifier
    fc_kernel<<<M_ROWS / 8, 256>>>(o1, fc_w, fc_b, out);
    #undef CONV
}

// round 13
// speedup vs baseline: 1.1169x; 1.0073x over previous
#include <cuda_runtime.h>
#include <cuda_bf16.h>
#include <cstdint>
#include <math.h>

// ---------------- problem constants ----------------
#define T_SEQ 1000
#define BATCH 16
#define M_ROWS (BATCH * T_SEQ)   // 16000
#define NBLK_R 16                // CTAs per LSTM direction (tensor-core rec)

// ---------------- fp32 scratch ----------------
__device__ float g_h1 [M_ROWS * 1024];
__device__ float g_h2 [(size_t)M_ROWS * 2560];
__device__ float g_xgf[M_ROWS * 1024];
__device__ float g_xgb[M_ROWS * 1024];
__device__ float g_out0[M_ROWS * 512];
__device__ float g_out1[M_ROWS * 512];
__device__ unsigned g_barctr[2];

// h exchange buffers for the tensor-core recurrence: bf16 hi/lo split
__device__ __nv_bfloat16 g_hbhi[2 * 2 * 4096];   // [dir][parity][16*256]
__device__ __nv_bfloat16 g_hblo[2 * 2 * 4096];

// ---------------- bf16 split scratch ----------------
__device__ __nv_bfloat16 g_xhi [M_ROWS * 80],    g_xlo [M_ROWS * 80];
__device__ __nv_bfloat16 g_w1hi[1024 * 80],      g_w1lo[1024 * 80];
__device__ __nv_bfloat16 g_w2hi[2560 * 1024],    g_w2lo[2560 * 1024];
__device__ __nv_bfloat16 g_h1hi[M_ROWS * 1024],  g_h1lo[M_ROWS * 1024];
__device__ __nv_bfloat16 g_h2hi[(size_t)M_ROWS * 2560], g_h2lo[(size_t)M_ROWS * 2560];
__device__ __nv_bfloat16 g_wl0fhi[1024 * 2560],  g_wl0flo[1024 * 2560];
__device__ __nv_bfloat16 g_wl0bhi[1024 * 2560],  g_wl0blo[1024 * 2560];
__device__ __nv_bfloat16 g_wl1fhi[1024 * 512],   g_wl1flo[1024 * 512];
__device__ __nv_bfloat16 g_wl1bhi[1024 * 512],   g_wl1blo[1024 * 512];
__device__ __nv_bfloat16 g_o0hi[M_ROWS * 512],   g_o0lo[M_ROWS * 512];
// W_hh splits (4 directions x [1024,256])
__device__ __nv_bfloat16 g_whh0fhi[1024 * 256], g_whh0flo[1024 * 256];
__device__ __nv_bfloat16 g_whh0bhi[1024 * 256], g_whh0blo[1024 * 256];
__device__ __nv_bfloat16 g_whh1fhi[1024 * 256], g_whh1flo[1024 * 256];
__device__ __nv_bfloat16 g_whh1bhi[1024 * 256], g_whh1blo[1024 * 256];

// ================= PTX helpers =================
__device__ __forceinline__ uint32_t smem_u32(const void* p) {
    uint32_t a;
    asm("{ .reg .u64 t; cvta.to.shared.u64 t, %1; cvt.u32.u64 %0, t; }" : "=r"(a) : "l"(p));
    return a;
}
__device__ __forceinline__ void cpa16(uint32_t dst, const void* src) {
    asm volatile("cp.async.cg.shared.global [%0], [%1], 16;" :: "r"(dst), "l"(src) : "memory");
}
__device__ __forceinline__ void sts_zero16(uint32_t dst) {
    asm volatile("st.shared.v4.b32 [%0], {%1,%1,%1,%1};" :: "r"(dst), "r"(0u) : "memory");
}
#define CP_COMMIT() asm volatile("cp.async.commit_group;" ::: "memory")
#define CP_WAIT1()  asm volatile("cp.async.wait_group 1;" ::: "memory")
#define CP_WAIT0()  asm volatile("cp.async.wait_group 0;" ::: "memory")

__device__ __forceinline__ void ldsm4(uint32_t addr, uint32_t& r0, uint32_t& r1,
                                      uint32_t& r2, uint32_t& r3) {
    asm volatile("ldmatrix.sync.aligned.m8n8.x4.shared.b16 {%0,%1,%2,%3}, [%4];"
                 : "=r"(r0), "=r"(r1), "=r"(r2), "=r"(r3) : "r"(addr));
}
__device__ __forceinline__ void mma_bf16(float* d, const uint32_t* a, const uint32_t* b) {
    asm volatile(
        "mma.sync.aligned.m16n8k16.row.col.f32.bf16.bf16.f32 "
        "{%0,%1,%2,%3}, {%4,%5,%6,%7}, {%8,%9}, {%0,%1,%2,%3};"
        : "+f"(d[0]), "+f"(d[1]), "+f"(d[2]), "+f"(d[3])
        : "r"(a[0]), "r"(a[1]), "r"(a[2]), "r"(a[3]), "r"(b[0]), "r"(b[1]));
}

// ---------------- fp32 -> bf16 hi/lo split kernel ----------------
__global__ void conv_split_kernel(const float* __restrict__ src,
                                  __nv_bfloat16* __restrict__ hi,
                                  __nv_bfloat16* __restrict__ lo, int n)
{
    int i = blockIdx.x * blockDim.x + threadIdx.x;
    if (i < n) {
        float v = src[i];
        __nv_bfloat16 h = __float2bfloat16_rn(v);
        hi[i] = h;
        lo[i] = __float2bfloat16_rn(v - __bfloat162float(h));
    }
}

// ================= tensor-core bf16x3 GEMM (round-8 proven, unchanged) ======
#define ROWB   80
#define TILEB  (128 * ROWB)
#define STAGEB (4 * TILEB)
#define GEMM_SMEM_BYTES (1024 + 2 * STAGEB)

__global__ __launch_bounds__(256, 2)
void tc_gemm(const __nv_bfloat16* __restrict__ Ahi, const __nv_bfloat16* __restrict__ Alo,
             const __nv_bfloat16* __restrict__ Bhi, const __nv_bfloat16* __restrict__ Blo,
             const float* __restrict__ bias1, const float* __restrict__ bias2,
             float* __restrict__ C,
             __nv_bfloat16* __restrict__ Chi, __nv_bfloat16* __restrict__ Clo,
             int M, int N, int K, int relu)
{
    extern __shared__ __align__(1024) char smem[];
    const int tid = threadIdx.x;
    const int wid = tid >> 5;
    const int lid = tid & 31;
    const int wm  = wid & 1;
    const int wn  = wid >> 1;
    const uint32_t sbase = smem_u32(smem);
    float* bsm = (float*)(smem);
    const uint32_t tiles = sbase + 1024;

    const int rowBase = blockIdx.y * 128;
    const int colBase = blockIdx.x * 128;

    if (tid < 128) bsm[tid] = bias1[colBase + tid] + (bias2 ? bias2[colBase + tid] : 0.f);

    float acc[4][4][4];
    #pragma unroll
    for (int i = 0; i < 4; i++)
        #pragma unroll
        for (int j = 0; j < 4; j++)
            #pragma unroll
            for (int q = 0; q < 4; q++) acc[i][j][q] = 0.f;

    const int NC = (K + 31) / 32;

    auto load_chunk = [&](int stage, int k0) {
        uint32_t base = tiles + stage * STAGEB;
        const int r  = tid >> 2;
        const int gc = tid & 3;
        const int k  = k0 + (gc << 3);
        #pragma unroll
        for (int i = 0; i < 8; i++) {
            const int part = i >> 1;
            const int row  = ((i & 1) << 6) + r;
            uint32_t dst = base + part * TILEB + row * ROWB + (gc << 4);
            const __nv_bfloat16* mat =
                (part == 0) ? Ahi : (part == 1) ? Alo : (part == 2) ? Bhi : Blo;
            const int gr = (part < 2) ? rowBase + row : colBase + row;
            if (k < K) cpa16(dst, mat + (size_t)gr * K + k);
            else       sts_zero16(dst);
        }
    };

    load_chunk(0, 0);
    CP_COMMIT();

    for (int c = 0; c < NC; c++) {
        if (c + 1 < NC) { load_chunk((c + 1) & 1, (c + 1) * 32); CP_COMMIT(); CP_WAIT1(); }
        else            { CP_WAIT0(); }
        __syncthreads();

        uint32_t abase = tiles + (c & 1) * STAGEB;
        uint32_t bbase = abase + 2 * TILEB;
        const int lm = lid >> 3;
        const int lr = lid & 7;

        #pragma unroll
        for (int ks = 0; ks < 2; ks++) {
            uint32_t ah[4][4], al[4][4], bh[4][2], bl[4][2];
            #pragma unroll
            for (int mt = 0; mt < 4; mt++) {
                uint32_t r = wm * 64 + mt * 16 + ((lm & 1) << 3) + lr;
                uint32_t addr = abase + r * ROWB + (ks << 5) + ((lm >> 1) << 4);
                ldsm4(addr,         ah[mt][0], ah[mt][1], ah[mt][2], ah[mt][3]);
                ldsm4(addr + TILEB, al[mt][0], al[mt][1], al[mt][2], al[mt][3]);
            }
            #pragma unroll
            for (int bt = 0; bt < 2; bt++) {
                uint32_t r = wn * 32 + bt * 16 + ((lm >> 1) << 3) + lr;
                uint32_t addr = bbase + r * ROWB + (ks << 5) + ((lm & 1) << 4);
                uint32_t t0, t1, t2, t3;
                ldsm4(addr, t0, t1, t2, t3);
                bh[2*bt][0] = t0; bh[2*bt][1] = t1; bh[2*bt+1][0] = t2; bh[2*bt+1][1] = t3;
                ldsm4(addr + TILEB, t0, t1, t2, t3);
                bl[2*bt][0] = t0; bl[2*bt][1] = t1; bl[2*bt+1][0] = t2; bl[2*bt+1][1] = t3;
            }
            #pragma unroll
            for (int mt = 0; mt < 4; mt++)
                #pragma unroll
                for (int nt = 0; nt < 4; nt++) {
                    mma_bf16(acc[mt][nt], ah[mt], bl[nt]);
                    mma_bf16(acc[mt][nt], al[mt], bh[nt]);
                    mma_bf16(acc[mt][nt], ah[mt], bh[nt]);
                }
        }
        __syncthreads();
    }

    const int g  = lid >> 2;
    const int tg = lid & 3;
    #pragma unroll
    for (int mt = 0; mt < 4; mt++) {
        int r0 = rowBase + wm * 64 + mt * 16 + g;
        #pragma unroll
        for (int nt = 0; nt < 4; nt++) {
            int cc = wn * 32 + nt * 8 + 2 * tg;
            float b0 = bsm[cc], b1 = bsm[cc + 1];
            float2 v0 = make_float2(acc[mt][nt][0] + b0, acc[mt][nt][1] + b1);
            float2 v1 = make_float2(acc[mt][nt][2] + b0, acc[mt][nt][3] + b1);
            if (relu) {
                v0.x = fmaxf(v0.x, 0.f); v0.y = fmaxf(v0.y, 0.f);
                v1.x = fmaxf(v1.x, 0.f); v1.y = fmaxf(v1.y, 0.f);
            }
            *(float2*)&C[(size_t)r0 * N + cc + colBase] = v0;
            *(float2*)&C[(size_t)(r0 + 8) * N + cc + colBase] = v1;
            if (Chi) {
                __nv_bfloat162 hh, ll;
                hh.x = __float2bfloat16_rn(v0.x);
                hh.y = __float2bfloat16_rn(v0.y);
                ll.x = __float2bfloat16_rn(v0.x - __bfloat162float(hh.x));
                ll.y = __float2bfloat16_rn(v0.y - __bfloat162float(hh.y));
                *(__nv_bfloat162*)&Chi[(size_t)r0 * N + cc + colBase] = hh;
                *(__nv_bfloat162*)&Clo[(size_t)r0 * N + cc + colBase] = ll;
                hh.x = __float2bfloat16_rn(v1.x);
                hh.y = __float2bfloat16_rn(v1.y);
                ll.x = __float2bfloat16_rn(v1.x - __bfloat162float(hh.x));
                ll.y = __float2bfloat16_rn(v1.y - __bfloat162float(hh.y));
                *(__nv_bfloat162*)&Chi[(size_t)(r0 + 8) * N + cc + colBase] = hh;
                *(__nv_bfloat162*)&Clo[(size_t)(r0 + 8) * N + cc + colBase] = ll;
            }
        }
    }
}

// ---------------- init: zero barrier counters + bf16 h buffers --------------
__global__ void init_rec_kernel()
{
    int t = blockIdx.x * blockDim.x + threadIdx.x;
    if (t < 2) g_barctr[t] = 0u;
    if (t < 2 * 2 * 4096) {
        g_hbhi[t] = __float2bfloat16_rn(0.f);
        g_hblo[t] = __float2bfloat16_rn(0.f);
    }
}

// ================= tensor-core persistent LSTM recurrence ====================
// 32 CTAs: dir = bx>>4, cb = bx&15. Each CTA owns 16 hidden units = 64 gate
// cols (unit-major: col = u*4 + gate). Per step: gates[16,64] =
// (Hhi+Hlo)@(Whi+Wlo)^T via bf16x3 mma (8 warps, one n8-tile each), + xg,
// shfl_xor(1) pairs (i,f)/(g,o), even lanes hold cell state for 2 batches.
// h republished as bf16 hi/lo through L2. Barrier = proven R8 protocol.
#define REC_W_HI 0
#define REC_W_LO 33792
#define REC_H_HI 67584
#define REC_H_LO 76032
#define REC_SMEM 84480

__global__ __launch_bounds__(256)
void lstm_rec_kernel(const float* __restrict__ xg_f, const float* __restrict__ xg_b,
                     const __nv_bfloat16* __restrict__ whhhi_f, const __nv_bfloat16* __restrict__ whhlo_f,
                     const __nv_bfloat16* __restrict__ whhhi_b, const __nv_bfloat16* __restrict__ whhlo_b,
                     float* __restrict__ out)
{
    extern __shared__ __align__(1024) char rsm[];
    const int dir = blockIdx.x >> 4;
    const int cb  = blockIdx.x & 15;
    const int tid = threadIdx.x;
    const int w   = tid >> 5;
    const int lid = tid & 31;
    const int lm  = lid >> 3, lr = lid & 7;
    const int gq  = lid >> 2, tg = lid & 3;

    const float* xg = dir ? xg_b : xg_f;
    const __nv_bfloat16* whi = dir ? whhhi_b : whhhi_f;
    const __nv_bfloat16* wlo = dir ? whhlo_b : whhlo_f;

    // load W_hh slice (64 gate cols x 256) into smem, pitch 528B
    for (int q = tid; q < 2048; q += 256) {
        int c  = q >> 5;
        int kb = q & 31;
        int R  = (c & 3) * 256 + 16 * cb + (c >> 2);  // gate*256 + unit
        *(uint4*)(rsm + REC_W_HI + c * 528 + kb * 16) =
            *(const uint4*)(whi + (size_t)R * 256 + kb * 8);
        *(uint4*)(rsm + REC_W_LO + c * 528 + kb * 16) =
            *(const uint4*)(wlo + (size_t)R * 256 + kb * 8);
    }

    const uint32_t sb = smem_u32(rsm);
    unsigned* ctr = &g_barctr[dir];
    __nv_bfloat16* hbhi = g_hbhi + dir * 2 * 4096;
    __nv_bfloat16* hblo = g_hblo + dir * 2 * 4096;

    // fragment base addresses (GEMM-validated ldsm patterns, pitch 528)
    const uint32_t aH = sb + REC_H_HI + ((lm & 1) * 8 + lr) * 528 + ((lm >> 1) << 4);
    const uint32_t aL = sb + REC_H_LO + ((lm & 1) * 8 + lr) * 528 + ((lm >> 1) << 4);
    const uint32_t bH = sb + REC_W_HI + (8 * w + lr) * 528 + (lm << 4);
    const uint32_t bL = sb + REC_W_LO + (8 * w + lr) * 528 + (lm << 4);

    const int c0 = 8 * w + 2 * tg;
    const int c1 = c0 + 1;
    const int xcol0 = (c0 & 3) * 256 + 16 * cb + (c0 >> 2);
    const int xcol1 = (c1 & 3) * 256 + 16 * cb + (c1 >> 2);
    const int junit = 16 * cb + 2 * w + (tg >> 1);

    float cs0 = 0.f, cs1 = 0.f;
    __syncthreads();

    {   // prime first timestep's xg
    }
    int tp = dir ? (T_SEQ - 1) : 0;
    float x00 = __ldg(&xg[(size_t)(gq * T_SEQ + tp) * 1024 + xcol0]);
    float x01 = __ldg(&xg[(size_t)(gq * T_SEQ + tp) * 1024 + xcol1]);
    float x10 = __ldg(&xg[(size_t)((gq + 8) * T_SEQ + tp) * 1024 + xcol0]);
    float x11 = __ldg(&xg[(size_t)((gq + 8) * T_SEQ + tp) * 1024 + xcol1]);

    for (int iter = 0; iter < T_SEQ; iter++) {
        const int par = iter & 1;
        const int t = dir ? (T_SEQ - 1 - iter) : iter;

        // load h (hi+lo) [16,256] bf16 into smem
        #pragma unroll
        for (int i = 0; i < 2; i++) {
            int q = tid + (i << 8);          // 0..511
            int row = q >> 5, kb = q & 31;
            *(uint4*)(rsm + REC_H_HI + row * 528 + kb * 16) =
                __ldcg((const uint4*)(hbhi + par * 4096 + row * 256 + kb * 8));
            *(uint4*)(rsm + REC_H_LO + row * 528 + kb * 16) =
                __ldcg((const uint4*)(hblo + par * 4096 + row * 256 + kb * 8));
        }
        __syncthreads();

        float acc[4] = {0.f, 0.f, 0.f, 0.f};
        #pragma unroll
        for (int kk = 0; kk < 8; kk++) {
            const uint32_t kb = kk * 64;
            uint32_t ah0[4], ah1[4], al0[4], al1[4], bh4[4], bl4[4];
            ldsm4(aH + kb,      ah0[0], ah0[1], ah0[2], ah0[3]);
            ldsm4(aH + kb + 32, ah1[0], ah1[1], ah1[2], ah1[3]);
            ldsm4(aL + kb,      al0[0], al0[1], al0[2], al0[3]);
            ldsm4(aL + kb + 32, al1[0], al1[1], al1[2], al1[3]);
            ldsm4(bH + kb,      bh4[0], bh4[1], bh4[2], bh4[3]);
            ldsm4(bL + kb,      bl4[0], bl4[1], bl4[2], bl4[3]);
            mma_bf16(acc, ah0, bl4);
            mma_bf16(acc, al0, bh4);
            mma_bf16(acc, ah0, bh4);
            mma_bf16(acc, ah1, bl4 + 2);
            mma_bf16(acc, al1, bh4 + 2);
            mma_bf16(acc, ah1, bh4 + 2);
        }

        acc[0] += x00; acc[1] += x01; acc[2] += x10; acc[3] += x11;
        float s0 = __shfl_xor_sync(0xffffffffu, acc[0], 1);
        float s1 = __shfl_xor_sync(0xffffffffu, acc[1], 1);
        float s2 = __shfl_xor_sync(0xffffffffu, acc[2], 1);
        float s3 = __shfl_xor_sync(0xffffffffu, acc[3], 1);

        float h0 = 0.f, h1 = 0.f;
        if ((tg & 1) == 0) {
            // even-tg lanes hold (i,f); partner supplied (g,o)
            float ii = 1.f / (1.f + expf(-acc[0]));
            float ff = 1.f / (1.f + expf(-acc[1]));
            float gg = tanhf(s0);
            float oo = 1.f / (1.f + expf(-s1));
            cs0 = ff * cs0 + ii * gg;
            h0 = oo * tanhf(cs0);
            ii = 1.f / (1.f + expf(-acc[2]));
            ff = 1.f / (1.f + expf(-acc[3]));
            gg = tanhf(s2);
            oo = 1.f / (1.f + expf(-s3));
            cs1 = ff * cs1 + ii * gg;
            h1 = oo * tanhf(cs1);

            __nv_bfloat16 hh0 = __float2bfloat16_rn(h0);
            __nv_bfloat16 hl0 = __float2bfloat16_rn(h0 - __bfloat162float(hh0));
            __nv_bfloat16 hh1 = __float2bfloat16_rn(h1);
            __nv_bfloat16 hl1 = __float2bfloat16_rn(h1 - __bfloat162float(hh1));
            const int np = par ^ 1;
            hbhi[np * 4096 + gq * 256 + junit] = hh0;
            hblo[np * 4096 + gq * 256 + junit] = hl0;
            hbhi[np * 4096 + (gq + 8) * 256 + junit] = hh1;
            hblo[np * 4096 + (gq + 8) * 256 + junit] = hl1;
            __threadfence();   // release: h visible before the arrival atomic
        }
        __syncthreads();       // all writers fenced before arrival

        if (tid == 0) atomicAdd(ctr, 1u);

        // off-critical-path: fp32 output + next xg prefetch
        if ((tg & 1) == 0) {
            out[(size_t)(gq * T_SEQ + t) * 512 + dir * 256 + junit] = h0;
            out[(size_t)((gq + 8) * T_SEQ + t) * 512 + dir * 256 + junit] = h1;
        }
        if (iter + 1 < T_SEQ) {
            int tn = dir ? (T_SEQ - 2 - iter) : (iter + 1);
            x00 = __ldg(&xg[(size_t)(gq * T_SEQ + tn) * 1024 + xcol0]);
            x01 = __ldg(&xg[(size_t)(gq * T_SEQ + tn) * 1024 + xcol1]);
            x10 = __ldg(&xg[(size_t)((gq + 8) * T_SEQ + tn) * 1024 + xcol0]);
            x11 = __ldg(&xg[(size_t)((gq + 8) * T_SEQ + tn) * 1024 + xcol1]);
        }

        if (tid == 0) {
            unsigned target = (unsigned)(iter + 1) * NBLK_R;
            while (*((volatile unsigned*)ctr) < target) { __nanosleep(32); }
        }
        __syncthreads();
        __threadfence();       // acquire: order next h loads after observation
    }
}

// ---------------- final FC: [16000,512] @ [29,512]^T + b -------------------
__global__ __launch_bounds__(256) void fc_kernel(
    const float* __restrict__ A, const float* __restrict__ W,
    const float* __restrict__ bias, float* __restrict__ out)
{
    __shared__ float as[8][512];
    int r0 = blockIdx.x * 8;
    for (int i = threadIdx.x; i < 8 * 512; i += 256)
        as[i >> 9][i & 511] = A[(size_t)(r0 + (i >> 9)) * 512 + (i & 511)];
    __syncthreads();

    int r = threadIdx.x >> 5;
    int c = threadIdx.x & 31;
    if (c < 29) {
        const float* w = W + c * 512;
        float acc = 0.f;
        #pragma unroll 8
        for (int k = 0; k < 512; k++) acc = fmaf(as[r][k], __ldg(&w[k]), acc);
        out[(size_t)(r0 + r) * 29 + c] = acc + bias[c];
    }
}

// ---------------- launch ---------------------------------------------------
extern "C" void kernel_launch(void* const* d_in, const int* in_sizes, int n_in,
                              void* d_out, int out_size)
{
    (void)in_sizes; (void)n_in; (void)out_size;
    const float* x        = (const float*)d_in[0];
    const float* fe_w1    = (const float*)d_in[1];
    const float* fe_b1    = (const float*)d_in[2];
    const float* fe_w2    = (const float*)d_in[3];
    const float* fe_b2    = (const float*)d_in[4];
    const float* w_ih_l0f = (const float*)d_in[5];
    const float* w_hh_l0f = (const float*)d_in[6];
    const float* b_ih_l0f = (const float*)d_in[7];
    const float* b_hh_l0f = (const float*)d_in[8];
    const float* w_ih_l0b = (const float*)d_in[9];
    const float* w_hh_l0b = (const float*)d_in[10];
    const float* b_ih_l0b = (const float*)d_in[11];
    const float* b_hh_l0b = (const float*)d_in[12];
    const float* w_ih_l1f = (const float*)d_in[13];
    const float* w_hh_l1f = (const float*)d_in[14];
    const float* b_ih_l1f = (const float*)d_in[15];
    const float* b_hh_l1f = (const float*)d_in[16];
    const float* w_ih_l1b = (const float*)d_in[17];
    const float* w_hh_l1b = (const float*)d_in[18];
    const float* b_ih_l1b = (const float*)d_in[19];
    const float* b_hh_l1b = (const float*)d_in[20];
    const float* fc_w     = (const float*)d_in[21];
    const float* fc_b     = (const float*)d_in[22];
    float* out = (float*)d_out;

    float *h1, *h2, *xgf, *xgb, *o0, *o1;
    cudaGetSymbolAddress((void**)&h1,  g_h1);
    cudaGetSymbolAddress((void**)&h2,  g_h2);
    cudaGetSymbolAddress((void**)&xgf, g_xgf);
    cudaGetSymbolAddress((void**)&xgb, g_xgb);
    cudaGetSymbolAddress((void**)&o0,  g_out0);
    cudaGetSymbolAddress((void**)&o1,  g_out1);

    __nv_bfloat16 *xhi, *xlo, *w1hi, *w1lo, *w2hi, *w2lo;
    __nv_bfloat16 *h1hi, *h1lo, *h2hi, *h2lo;
    __nv_bfloat16 *wl0fhi, *wl0flo, *wl0bhi, *wl0blo;
    __nv_bfloat16 *wl1fhi, *wl1flo, *wl1bhi, *wl1blo, *o0hi, *o0lo;
    __nv_bfloat16 *wh0fhi, *wh0flo, *wh0bhi, *wh0blo;
    __nv_bfloat16 *wh1fhi, *wh1flo, *wh1bhi, *wh1blo;
    cudaGetSymbolAddress((void**)&xhi,    g_xhi);    cudaGetSymbolAddress((void**)&xlo,    g_xlo);
    cudaGetSymbolAddress((void**)&w1hi,   g_w1hi);   cudaGetSymbolAddress((void**)&w1lo,   g_w1lo);
    cudaGetSymbolAddress((void**)&w2hi,   g_w2hi);   cudaGetSymbolAddress((void**)&w2lo,   g_w2lo);
    cudaGetSymbolAddress((void**)&h1hi,   g_h1hi);   cudaGetSymbolAddress((void**)&h1lo,   g_h1lo);
    cudaGetSymbolAddress((void**)&h2hi,   g_h2hi);   cudaGetSymbolAddress((void**)&h2lo,   g_h2lo);
    cudaGetSymbolAddress((void**)&wl0fhi, g_wl0fhi); cudaGetSymbolAddress((void**)&wl0flo, g_wl0flo);
    cudaGetSymbolAddress((void**)&wl0bhi, g_wl0bhi); cudaGetSymbolAddress((void**)&wl0blo, g_wl0blo);
    cudaGetSymbolAddress((void**)&wl1fhi, g_wl1fhi); cudaGetSymbolAddress((void**)&wl1flo, g_wl1flo);
    cudaGetSymbolAddress((void**)&wl1bhi, g_wl1bhi); cudaGetSymbolAddress((void**)&wl1blo, g_wl1blo);
    cudaGetSymbolAddress((void**)&o0hi,   g_o0hi);   cudaGetSymbolAddress((void**)&o0lo,   g_o0lo);
    cudaGetSymbolAddress((void**)&wh0fhi, g_whh0fhi); cudaGetSymbolAddress((void**)&wh0flo, g_whh0flo);
    cudaGetSymbolAddress((void**)&wh0bhi, g_whh0bhi); cudaGetSymbolAddress((void**)&wh0blo, g_whh0blo);
    cudaGetSymbolAddress((void**)&wh1fhi, g_whh1fhi); cudaGetSymbolAddress((void**)&wh1flo, g_whh1flo);
    cudaGetSymbolAddress((void**)&wh1bhi, g_whh1bhi); cudaGetSymbolAddress((void**)&wh1blo, g_whh1blo);

    cudaFuncSetAttribute(tc_gemm, cudaFuncAttributeMaxDynamicSharedMemorySize, GEMM_SMEM_BYTES);
    cudaFuncSetAttribute(lstm_rec_kernel, cudaFuncAttributeMaxDynamicSharedMemorySize, REC_SMEM);

    #define CONV(src, hi, lo, n) conv_split_kernel<<<((n) + 255) / 256, 256>>>(src, hi, lo, n)
    CONV(x, xhi, xlo, M_ROWS * 80);
    CONV(fe_w1, w1hi, w1lo, 1024 * 80);
    CONV(fe_w2, w2hi, w2lo, 2560 * 1024);
    CONV(w_ih_l0f, wl0fhi, wl0flo, 1024 * 2560);
    CONV(w_ih_l0b, wl0bhi, wl0blo, 1024 * 2560);
    CONV(w_ih_l1f, wl1fhi, wl1flo, 1024 * 512);
    CONV(w_ih_l1b, wl1bhi, wl1blo, 1024 * 512);
    CONV(w_hh_l0f, wh0fhi, wh0flo, 1024 * 256);
    CONV(w_hh_l0b, wh0bhi, wh0blo, 1024 * 256);
    CONV(w_hh_l1f, wh1fhi, wh1flo, 1024 * 256);
    CONV(w_hh_l1b, wh1bhi, wh1blo, 1024 * 256);

    // feature extractor
    tc_gemm<<<dim3(8,  M_ROWS / 128), 256, GEMM_SMEM_BYTES>>>(
        xhi, xlo, w1hi, w1lo, fe_b1, nullptr, h1, h1hi, h1lo, M_ROWS, 1024, 80, 1);
    tc_gemm<<<dim3(20, M_ROWS / 128), 256, GEMM_SMEM_BYTES>>>(
        h1hi, h1lo, w2hi, w2lo, fe_b2, nullptr, h2, h2hi, h2lo, M_ROWS, 2560, 1024, 1);

    // layer 0: gate precompute + recurrence
    tc_gemm<<<dim3(8, M_ROWS / 128), 256, GEMM_SMEM_BYTES>>>(
        h2hi, h2lo, wl0fhi, wl0flo, b_ih_l0f, b_hh_l0f, xgf, nullptr, nullptr, M_ROWS, 1024, 2560, 0);
    tc_gemm<<<dim3(8, M_ROWS / 128), 256, GEMM_SMEM_BYTES>>>(
        h2hi, h2lo, wl0bhi, wl0blo, b_ih_l0b, b_hh_l0b, xgb, nullptr, nullptr, M_ROWS, 1024, 2560, 0);
    init_rec_kernel<<<64, 256>>>();
    lstm_rec_kernel<<<2 * NBLK_R, 256, REC_SMEM>>>(
        xgf, xgb, wh0fhi, wh0flo, wh0bhi, wh0blo, o0);

    // layer 1
    CONV(o0, o0hi, o0lo, M_ROWS * 512);
    tc_gemm<<<dim3(8, M_ROWS / 128), 256, GEMM_SMEM_BYTES>>>(
        o0hi, o0lo, wl1fhi, wl1flo, b_ih_l1f, b_hh_l1f, xgf, nullptr, nullptr, M_ROWS, 1024, 512, 0);
    tc_gemm<<<dim3(8, M_ROWS / 128), 256, GEMM_SMEM_BYTES>>>(
        o0hi, o0lo, wl1bhi, wl1blo, b_ih_l1b, b_hh_l1b, xgb, nullptr, nullptr, M_ROWS, 1024, 512, 0);
    init_rec_kernel<<<64, 256>>>();
    lstm_rec_kernel<<<2 * NBLK_R, 256, REC_SMEM>>>(
        xgf, xgb, wh1fhi, wh1flo, wh1bhi, wh1blo, o1);

    // classifier
    fc_kernel<<<M_ROWS / 8, 256>>>(o1, fc_w, fc_b, out);
    #undef CONV
}

// round 15
// speedup vs baseline: 1.1255x; 1.0078x over previous
#include <cuda_runtime.h>
#include <cuda_bf16.h>
#include <cstdint>
#include <math.h>

// ---------------- problem constants ----------------
#define T_SEQ 1000
#define BATCH 16
#define M_ROWS (BATCH * T_SEQ)   // 16000
#define NBLK_R 16                // CTAs per LSTM direction (tensor-core rec)

// ---------------- fp32 scratch ----------------
__device__ float g_h1 [M_ROWS * 1024];
__device__ float g_h2 [(size_t)M_ROWS * 2560];
__device__ float g_xgf[M_ROWS * 1024];
__device__ float g_xgb[M_ROWS * 1024];
__device__ float g_out0[M_ROWS * 512];
__device__ float g_out1[M_ROWS * 512];
__device__ unsigned g_barctr[2];

// h exchange buffers for the tensor-core recurrence: bf16 hi/lo split
__device__ __nv_bfloat16 g_hbhi[2 * 2 * 4096];   // [dir][parity][16*256]
__device__ __nv_bfloat16 g_hblo[2 * 2 * 4096];

// ---------------- bf16 split scratch ----------------
__device__ __nv_bfloat16 g_xhi [M_ROWS * 80],    g_xlo [M_ROWS * 80];
__device__ __nv_bfloat16 g_w1hi[1024 * 80],      g_w1lo[1024 * 80];
__device__ __nv_bfloat16 g_w2hi[2560 * 1024],    g_w2lo[2560 * 1024];
__device__ __nv_bfloat16 g_h1hi[M_ROWS * 1024],  g_h1lo[M_ROWS * 1024];
__device__ __nv_bfloat16 g_h2hi[(size_t)M_ROWS * 2560], g_h2lo[(size_t)M_ROWS * 2560];
__device__ __nv_bfloat16 g_wl0fhi[1024 * 2560],  g_wl0flo[1024 * 2560];
__device__ __nv_bfloat16 g_wl0bhi[1024 * 2560],  g_wl0blo[1024 * 2560];
__device__ __nv_bfloat16 g_wl1fhi[1024 * 512],   g_wl1flo[1024 * 512];
__device__ __nv_bfloat16 g_wl1bhi[1024 * 512],   g_wl1blo[1024 * 512];
__device__ __nv_bfloat16 g_o0hi[M_ROWS * 512],   g_o0lo[M_ROWS * 512];
// W_hh splits (4 directions x [1024,256])
__device__ __nv_bfloat16 g_whh0fhi[1024 * 256], g_whh0flo[1024 * 256];
__device__ __nv_bfloat16 g_whh0bhi[1024 * 256], g_whh0blo[1024 * 256];
__device__ __nv_bfloat16 g_whh1fhi[1024 * 256], g_whh1flo[1024 * 256];
__device__ __nv_bfloat16 g_whh1bhi[1024 * 256], g_whh1blo[1024 * 256];

// ================= PTX helpers =================
__device__ __forceinline__ uint32_t smem_u32(const void* p) {
    uint32_t a;
    asm("{ .reg .u64 t; cvta.to.shared.u64 t, %1; cvt.u32.u64 %0, t; }" : "=r"(a) : "l"(p));
    return a;
}
__device__ __forceinline__ void cpa16(uint32_t dst, const void* src) {
    asm volatile("cp.async.cg.shared.global [%0], [%1], 16;" :: "r"(dst), "l"(src) : "memory");
}
__device__ __forceinline__ void sts_zero16(uint32_t dst) {
    asm volatile("st.shared.v4.b32 [%0], {%1,%1,%1,%1};" :: "r"(dst), "r"(0u) : "memory");
}
#define CP_COMMIT() asm volatile("cp.async.commit_group;" ::: "memory")
#define CP_WAIT0()  asm volatile("cp.async.wait_group 0;" ::: "memory")

__device__ __forceinline__ void ldsm4(uint32_t addr, uint32_t& r0, uint32_t& r1,
                                      uint32_t& r2, uint32_t& r3) {
    asm volatile("ldmatrix.sync.aligned.m8n8.x4.shared.b16 {%0,%1,%2,%3}, [%4];"
                 : "=r"(r0), "=r"(r1), "=r"(r2), "=r"(r3) : "r"(addr));
}
__device__ __forceinline__ void mma_bf16(float* d, const uint32_t* a, const uint32_t* b) {
    asm volatile(
        "mma.sync.aligned.m16n8k16.row.col.f32.bf16.bf16.f32 "
        "{%0,%1,%2,%3}, {%4,%5,%6,%7}, {%8,%9}, {%0,%1,%2,%3};"
        : "+f"(d[0]), "+f"(d[1]), "+f"(d[2]), "+f"(d[3])
        : "r"(a[0]), "r"(a[1]), "r"(a[2]), "r"(a[3]), "r"(b[0]), "r"(b[1]));
}

// ---------------- fp32 -> bf16 hi/lo split kernel ----------------
__global__ void conv_split_kernel(const float* __restrict__ src,
                                  __nv_bfloat16* __restrict__ hi,
                                  __nv_bfloat16* __restrict__ lo, int n)
{
    int i = blockIdx.x * blockDim.x + threadIdx.x;
    if (i < n) {
        float v = src[i];
        __nv_bfloat16 h = __float2bfloat16_rn(v);
        hi[i] = h;
        lo[i] = __float2bfloat16_rn(v - __bfloat162float(h));
    }
}

// ================= tensor-core bf16x3 GEMM =================
// C = A @ Bw^T + bias, opt ReLU.  A,Bw as bf16 hi/lo.
// MERGED second GEMM sharing A: blocks with blockIdx.x >= nxHalf use
// (B2, bias1b/bias2b, C2). Single __syncthreads per K-chunk; exactly one
// cp.async group in flight (WAIT0 -> sync -> issue next -> compute).
#define ROWB   80
#define TILEB  (128 * ROWB)
#define STAGEB (4 * TILEB)
#define GEMM_SMEM_BYTES (1024 + 2 * STAGEB)

__global__ __launch_bounds__(256, 2)
void tc_gemm(const __nv_bfloat16* __restrict__ Ahi, const __nv_bfloat16* __restrict__ Alo,
             const __nv_bfloat16* __restrict__ Bhi, const __nv_bfloat16* __restrict__ Blo,
             const __nv_bfloat16* __restrict__ B2hi, const __nv_bfloat16* __restrict__ B2lo,
             const float* __restrict__ bias1, const float* __restrict__ bias2,
             const float* __restrict__ bias1b, const float* __restrict__ bias2b,
             float* __restrict__ C, float* __restrict__ C2,
             __nv_bfloat16* __restrict__ Chi, __nv_bfloat16* __restrict__ Clo,
             int M, int N, int K, int relu, int nxHalf)
{
    extern __shared__ __align__(1024) char smem[];
    const int tid = threadIdx.x;
    const int wid = tid >> 5;
    const int lid = tid & 31;
    const int wm  = wid & 1;
    const int wn  = wid >> 1;
    const uint32_t sbase = smem_u32(smem);
    float* bsm = (float*)(smem);
    const uint32_t tiles = sbase + 1024;

    // merged-half selection
    int bx = blockIdx.x;
    const __nv_bfloat16* bhi = Bhi;
    const __nv_bfloat16* blo = Blo;
    const float* b1 = bias1;
    const float* b2 = bias2;
    float* Cout = C;
    if (B2hi != nullptr && bx >= nxHalf) {
        bx -= nxHalf;
        bhi = B2hi; blo = B2lo; b1 = bias1b; b2 = bias2b; Cout = C2;
    }
    const int rowBase = blockIdx.y * 128;
    const int colBase = bx * 128;

    if (tid < 128) bsm[tid] = b1[colBase + tid] + (b2 ? b2[colBase + tid] : 0.f);

    float acc[4][4][4];
    #pragma unroll
    for (int i = 0; i < 4; i++)
        #pragma unroll
        for (int j = 0; j < 4; j++)
            #pragma unroll
            for (int q = 0; q < 4; q++) acc[i][j][q] = 0.f;

    const int NC = (K + 31) / 32;

    auto load_chunk = [&](int stage, int k0) {
        uint32_t base = tiles + stage * STAGEB;
        const int r  = tid >> 2;
        const int gc = tid & 3;
        const int k  = k0 + (gc << 3);
        #pragma unroll
        for (int i = 0; i < 8; i++) {
            const int part = i >> 1;
            const int row  = ((i & 1) << 6) + r;
            uint32_t dst = base + part * TILEB + row * ROWB + (gc << 4);
            const __nv_bfloat16* mat =
                (part == 0) ? Ahi : (part == 1) ? Alo : (part == 2) ? bhi : blo;
            const int gr = (part < 2) ? rowBase + row : colBase + row;
            if (k < K) cpa16(dst, mat + (size_t)gr * K + k);
            else       sts_zero16(dst);
        }
    };

    load_chunk(0, 0);
    CP_COMMIT();

    for (int c = 0; c < NC; c++) {
        CP_WAIT0();                               // chunk c fully resident
        __syncthreads();                          // compute(c-1) done everywhere
        if (c + 1 < NC) { load_chunk((c + 1) & 1, (c + 1) * 32); CP_COMMIT(); }

        uint32_t abase = tiles + (c & 1) * STAGEB;
        uint32_t bbase = abase + 2 * TILEB;
        const int lm = lid >> 3;
        const int lr = lid & 7;

        #pragma unroll
        for (int ks = 0; ks < 2; ks++) {
            uint32_t ah[4][4], al[4][4], bh[4][2], bl[4][2];
            #pragma unroll
            for (int mt = 0; mt < 4; mt++) {
                uint32_t r = wm * 64 + mt * 16 + ((lm & 1) << 3) + lr;
                uint32_t addr = abase + r * ROWB + (ks << 5) + ((lm >> 1) << 4);
                ldsm4(addr,         ah[mt][0], ah[mt][1], ah[mt][2], ah[mt][3]);
                ldsm4(addr + TILEB, al[mt][0], al[mt][1], al[mt][2], al[mt][3]);
            }
            #pragma unroll
            for (int bt = 0; bt < 2; bt++) {
                uint32_t r = wn * 32 + bt * 16 + ((lm >> 1) << 3) + lr;
                uint32_t addr = bbase + r * ROWB + (ks << 5) + ((lm & 1) << 4);
                uint32_t t0, t1, t2, t3;
                ldsm4(addr, t0, t1, t2, t3);
                bh[2*bt][0] = t0; bh[2*bt][1] = t1; bh[2*bt+1][0] = t2; bh[2*bt+1][1] = t3;
                ldsm4(addr + TILEB, t0, t1, t2, t3);
                bl[2*bt][0] = t0; bl[2*bt][1] = t1; bl[2*bt+1][0] = t2; bl[2*bt+1][1] = t3;
            }
            #pragma unroll
            for (int mt = 0; mt < 4; mt++)
                #pragma unroll
                for (int nt = 0; nt < 4; nt++) {
                    mma_bf16(acc[mt][nt], ah[mt], bl[nt]);
                    mma_bf16(acc[mt][nt], al[mt], bh[nt]);
                    mma_bf16(acc[mt][nt], ah[mt], bh[nt]);
                }
        }
    }

    const int g  = lid >> 2;
    const int tg = lid & 3;
    #pragma unroll
    for (int mt = 0; mt < 4; mt++) {
        int r0 = rowBase + wm * 64 + mt * 16 + g;
        #pragma unroll
        for (int nt = 0; nt < 4; nt++) {
            int cc = wn * 32 + nt * 8 + 2 * tg;
            float b0 = bsm[cc], b1v = bsm[cc + 1];
            float2 v0 = make_float2(acc[mt][nt][0] + b0, acc[mt][nt][1] + b1v);
            float2 v1 = make_float2(acc[mt][nt][2] + b0, acc[mt][nt][3] + b1v);
            if (relu) {
                v0.x = fmaxf(v0.x, 0.f); v0.y = fmaxf(v0.y, 0.f);
                v1.x = fmaxf(v1.x, 0.f); v1.y = fmaxf(v1.y, 0.f);
            }
            *(float2*)&Cout[(size_t)r0 * N + cc + colBase] = v0;
            *(float2*)&Cout[(size_t)(r0 + 8) * N + cc + colBase] = v1;
            if (Chi) {
                __nv_bfloat162 hh, ll;
                hh.x = __float2bfloat16_rn(v0.x);
                hh.y = __float2bfloat16_rn(v0.y);
                ll.x = __float2bfloat16_rn(v0.x - __bfloat162float(hh.x));
                ll.y = __float2bfloat16_rn(v0.y - __bfloat162float(hh.y));
                *(__nv_bfloat162*)&Chi[(size_t)r0 * N + cc + colBase] = hh;
                *(__nv_bfloat162*)&Clo[(size_t)r0 * N + cc + colBase] = ll;
                hh.x = __float2bfloat16_rn(v1.x);
                hh.y = __float2bfloat16_rn(v1.y);
                ll.x = __float2bfloat16_rn(v1.x - __bfloat162float(hh.x));
                ll.y = __float2bfloat16_rn(v1.y - __bfloat162float(hh.y));
                *(__nv_bfloat162*)&Chi[(size_t)(r0 + 8) * N + cc + colBase] = hh;
                *(__nv_bfloat162*)&Clo[(size_t)(r0 + 8) * N + cc + colBase] = ll;
            }
        }
    }
}

// ---------------- init: zero barrier counters + bf16 h buffers --------------
__global__ void init_rec_kernel()
{
    int t = blockIdx.x * blockDim.x + threadIdx.x;
    if (t < 2) g_barctr[t] = 0u;
    if (t < 2 * 2 * 4096) {
        g_hbhi[t] = __float2bfloat16_rn(0.f);
        g_hblo[t] = __float2bfloat16_rn(0.f);
    }
}

// ================= tensor-core persistent LSTM recurrence (R13, proven) =====
#define REC_W_HI 0
#define REC_W_LO 33792
#define REC_H_HI 67584
#define REC_H_LO 76032
#define REC_SMEM 84480

__global__ __launch_bounds__(256)
void lstm_rec_kernel(const float* __restrict__ xg_f, const float* __restrict__ xg_b,
                     const __nv_bfloat16* __restrict__ whhhi_f, const __nv_bfloat16* __restrict__ whhlo_f,
                     const __nv_bfloat16* __restrict__ whhhi_b, const __nv_bfloat16* __restrict__ whhlo_b,
                     float* __restrict__ out)
{
    extern __shared__ __align__(1024) char rsm[];
    const int dir = blockIdx.x >> 4;
    const int cb  = blockIdx.x & 15;
    const int tid = threadIdx.x;
    const int w   = tid >> 5;
    const int lid = tid & 31;
    const int lm  = lid >> 3, lr = lid & 7;
    const int gq  = lid >> 2, tg = lid & 3;

    const float* xg = dir ? xg_b : xg_f;
    const __nv_bfloat16* whi = dir ? whhhi_b : whhhi_f;
    const __nv_bfloat16* wlo = dir ? whhlo_b : whhlo_f;

    for (int q = tid; q < 2048; q += 256) {
        int c  = q >> 5;
        int kb = q & 31;
        int R  = (c & 3) * 256 + 16 * cb + (c >> 2);
        *(uint4*)(rsm + REC_W_HI + c * 528 + kb * 16) =
            *(const uint4*)(whi + (size_t)R * 256 + kb * 8);
        *(uint4*)(rsm + REC_W_LO + c * 528 + kb * 16) =
            *(const uint4*)(wlo + (size_t)R * 256 + kb * 8);
    }

    const uint32_t sb = smem_u32(rsm);
    unsigned* ctr = &g_barctr[dir];
    __nv_bfloat16* hbhi = g_hbhi + dir * 2 * 4096;
    __nv_bfloat16* hblo = g_hblo + dir * 2 * 4096;

    const uint32_t aH = sb + REC_H_HI + ((lm & 1) * 8 + lr) * 528 + ((lm >> 1) << 4);
    const uint32_t aL = sb + REC_H_LO + ((lm & 1) * 8 + lr) * 528 + ((lm >> 1) << 4);
    const uint32_t bH = sb + REC_W_HI + (8 * w + lr) * 528 + (lm << 4);
    const uint32_t bL = sb + REC_W_LO + (8 * w + lr) * 528 + (lm << 4);

    const int c0 = 8 * w + 2 * tg;
    const int c1 = c0 + 1;
    const int xcol0 = (c0 & 3) * 256 + 16 * cb + (c0 >> 2);
    const int xcol1 = (c1 & 3) * 256 + 16 * cb + (c1 >> 2);
    const int junit = 16 * cb + 2 * w + (tg >> 1);

    float cs0 = 0.f, cs1 = 0.f;
    __syncthreads();

    int tp = dir ? (T_SEQ - 1) : 0;
    float x00 = __ldg(&xg[(size_t)(gq * T_SEQ + tp) * 1024 + xcol0]);
    float x01 = __ldg(&xg[(size_t)(gq * T_SEQ + tp) * 1024 + xcol1]);
    float x10 = __ldg(&xg[(size_t)((gq + 8) * T_SEQ + tp) * 1024 + xcol0]);
    float x11 = __ldg(&xg[(size_t)((gq + 8) * T_SEQ + tp) * 1024 + xcol1]);

    for (int iter = 0; iter < T_SEQ; iter++) {
        const int par = iter & 1;
        const int t = dir ? (T_SEQ - 1 - iter) : iter;

        #pragma unroll
        for (int i = 0; i < 2; i++) {
            int q = tid + (i << 8);
            int row = q >> 5, kb = q & 31;
            *(uint4*)(rsm + REC_H_HI + row * 528 + kb * 16) =
                __ldcg((const uint4*)(hbhi + par * 4096 + row * 256 + kb * 8));
            *(uint4*)(rsm + REC_H_LO + row * 528 + kb * 16) =
                __ldcg((const uint4*)(hblo + par * 4096 + row * 256 + kb * 8));
        }
        __syncthreads();

        float acc[4] = {0.f, 0.f, 0.f, 0.f};
        #pragma unroll
        for (int kk = 0; kk < 8; kk++) {
            const uint32_t kb = kk * 64;
            uint32_t ah0[4], ah1[4], al0[4], al1[4], bh4[4], bl4[4];
            ldsm4(aH + kb,      ah0[0], ah0[1], ah0[2], ah0[3]);
            ldsm4(aH + kb + 32, ah1[0], ah1[1], ah1[2], ah1[3]);
            ldsm4(aL + kb,      al0[0], al0[1], al0[2], al0[3]);
            ldsm4(aL + kb + 32, al1[0], al1[1], al1[2], al1[3]);
            ldsm4(bH + kb,      bh4[0], bh4[1], bh4[2], bh4[3]);
            ldsm4(bL + kb,      bl4[0], bl4[1], bl4[2], bl4[3]);
            mma_bf16(acc, ah0, bl4);
            mma_bf16(acc, al0, bh4);
            mma_bf16(acc, ah0, bh4);
            mma_bf16(acc, ah1, bl4 + 2);
            mma_bf16(acc, al1, bh4 + 2);
            mma_bf16(acc, ah1, bh4 + 2);
        }

        acc[0] += x00; acc[1] += x01; acc[2] += x10; acc[3] += x11;
        float s0 = __shfl_xor_sync(0xffffffffu, acc[0], 1);
        float s1 = __shfl_xor_sync(0xffffffffu, acc[1], 1);
        float s2 = __shfl_xor_sync(0xffffffffu, acc[2], 1);
        float s3 = __shfl_xor_sync(0xffffffffu, acc[3], 1);

        float h0 = 0.f, h1 = 0.f;
        if ((tg & 1) == 0) {
            float ii = 1.f / (1.f + expf(-acc[0]));
            float ff = 1.f / (1.f + expf(-acc[1]));
            float gg = tanhf(s0);
            float oo = 1.f / (1.f + expf(-s1));
            cs0 = ff * cs0 + ii * gg;
            h0 = oo * tanhf(cs0);
            ii = 1.f / (1.f + expf(-acc[2]));
            ff = 1.f / (1.f + expf(-acc[3]));
            gg = tanhf(s2);
            oo = 1.f / (1.f + expf(-s3));
            cs1 = ff * cs1 + ii * gg;
            h1 = oo * tanhf(cs1);

            __nv_bfloat16 hh0 = __float2bfloat16_rn(h0);
            __nv_bfloat16 hl0 = __float2bfloat16_rn(h0 - __bfloat162float(hh0));
            __nv_bfloat16 hh1 = __float2bfloat16_rn(h1);
            __nv_bfloat16 hl1 = __float2bfloat16_rn(h1 - __bfloat162float(hh1));
            const int np = par ^ 1;
            hbhi[np * 4096 + gq * 256 + junit] = hh0;
            hblo[np * 4096 + gq * 256 + junit] = hl0;
            hbhi[np * 4096 + (gq + 8) * 256 + junit] = hh1;
            hblo[np * 4096 + (gq + 8) * 256 + junit] = hl1;
            __threadfence();
        }
        __syncthreads();

        if (tid == 0) atomicAdd(ctr, 1u);

        if ((tg & 1) == 0) {
            out[(size_t)(gq * T_SEQ + t) * 512 + dir * 256 + junit] = h0;
            out[(size_t)((gq + 8) * T_SEQ + t) * 512 + dir * 256 + junit] = h1;
        }
        if (iter + 1 < T_SEQ) {
            int tn = dir ? (T_SEQ - 2 - iter) : (iter + 1);
            x00 = __ldg(&xg[(size_t)(gq * T_SEQ + tn) * 1024 + xcol0]);
            x01 = __ldg(&xg[(size_t)(gq * T_SEQ + tn) * 1024 + xcol1]);
            x10 = __ldg(&xg[(size_t)((gq + 8) * T_SEQ + tn) * 1024 + xcol0]);
            x11 = __ldg(&xg[(size_t)((gq + 8) * T_SEQ + tn) * 1024 + xcol1]);
        }

        if (tid == 0) {
            unsigned target = (unsigned)(iter + 1) * NBLK_R;
            while (*((volatile unsigned*)ctr) < target) { __nanosleep(32); }
        }
        __syncthreads();
        __threadfence();
    }
}

// ---------------- final FC: [16000,512] @ [29,512]^T + b -------------------
__global__ __launch_bounds__(256) void fc_kernel(
    const float* __restrict__ A, const float* __restrict__ W,
    const float* __restrict__ bias, float* __restrict__ out)
{
    __shared__ float as[8][512];
    int r0 = blockIdx.x * 8;
    for (int i = threadIdx.x; i < 8 * 512; i += 256)
        as[i >> 9][i & 511] = A[(size_t)(r0 + (i >> 9)) * 512 + (i & 511)];
    __syncthreads();

    int r = threadIdx.x >> 5;
    int c = threadIdx.x & 31;
    if (c < 29) {
        const float* w = W + c * 512;
        float acc = 0.f;
        #pragma unroll 8
        for (int k = 0; k < 512; k++) acc = fmaf(as[r][k], __ldg(&w[k]), acc);
        out[(size_t)(r0 + r) * 29 + c] = acc + bias[c];
    }
}

// ---------------- launch ---------------------------------------------------
extern "C" void kernel_launch(void* const* d_in, const int* in_sizes, int n_in,
                              void* d_out, int out_size)
{
    (void)in_sizes; (void)n_in; (void)out_size;
    const float* x        = (const float*)d_in[0];
    const float* fe_w1    = (const float*)d_in[1];
    const float* fe_b1    = (const float*)d_in[2];
    const float* fe_w2    = (const float*)d_in[3];
    const float* fe_b2    = (const float*)d_in[4];
    const float* w_ih_l0f = (const float*)d_in[5];
    const float* w_hh_l0f = (const float*)d_in[6];
    const float* b_ih_l0f = (const float*)d_in[7];
    const float* b_hh_l0f = (const float*)d_in[8];
    const float* w_ih_l0b = (const float*)d_in[9];
    const float* w_hh_l0b = (const float*)d_in[10];
    const float* b_ih_l0b = (const float*)d_in[11];
    const float* b_hh_l0b = (const float*)d_in[12];
    const float* w_ih_l1f = (const float*)d_in[13];
    const float* w_hh_l1f = (const float*)d_in[14];
    const float* b_ih_l1f = (const float*)d_in[15];
    const float* b_hh_l1f = (const float*)d_in[16];
    const float* w_ih_l1b = (const float*)d_in[17];
    const float* w_hh_l1b = (const float*)d_in[18];
    const float* b_ih_l1b = (const float*)d_in[19];
    const float* b_hh_l1b = (const float*)d_in[20];
    const float* fc_w     = (const float*)d_in[21];
    const float* fc_b     = (const float*)d_in[22];
    float* out = (float*)d_out;

    float *h1, *h2, *xgf, *xgb, *o0, *o1;
    cudaGetSymbolAddress((void**)&h1,  g_h1);
    cudaGetSymbolAddress((void**)&h2,  g_h2);
    cudaGetSymbolAddress((void**)&xgf, g_xgf);
    cudaGetSymbolAddress((void**)&xgb, g_xgb);
    cudaGetSymbolAddress((void**)&o0,  g_out0);
    cudaGetSymbolAddress((void**)&o1,  g_out1);

    __nv_bfloat16 *xhi, *xlo, *w1hi, *w1lo, *w2hi, *w2lo;
    __nv_bfloat16 *h1hi, *h1lo, *h2hi, *h2lo;
    __nv_bfloat16 *wl0fhi, *wl0flo, *wl0bhi, *wl0blo;
    __nv_bfloat16 *wl1fhi, *wl1flo, *wl1bhi, *wl1blo, *o0hi, *o0lo;
    __nv_bfloat16 *wh0fhi, *wh0flo, *wh0bhi, *wh0blo;
    __nv_bfloat16 *wh1fhi, *wh1flo, *wh1bhi, *wh1blo;
    cudaGetSymbolAddress((void**)&xhi,    g_xhi);    cudaGetSymbolAddress((void**)&xlo,    g_xlo);
    cudaGetSymbolAddress((void**)&w1hi,   g_w1hi);   cudaGetSymbolAddress((void**)&w1lo,   g_w1lo);
    cudaGetSymbolAddress((void**)&w2hi,   g_w2hi);   cudaGetSymbolAddress((void**)&w2lo,   g_w2lo);
    cudaGetSymbolAddress((void**)&h1hi,   g_h1hi);   cudaGetSymbolAddress((void**)&h1lo,   g_h1lo);
    cudaGetSymbolAddress((void**)&h2hi,   g_h2hi);   cudaGetSymbolAddress((void**)&h2lo,   g_h2lo);
    cudaGetSymbolAddress((void**)&wl0fhi, g_wl0fhi); cudaGetSymbolAddress((void**)&wl0flo, g_wl0flo);
    cudaGetSymbolAddress((void**)&wl0bhi, g_wl0bhi); cudaGetSymbolAddress((void**)&wl0blo, g_wl0blo);
    cudaGetSymbolAddress((void**)&wl1fhi, g_wl1fhi); cudaGetSymbolAddress((void**)&wl1flo, g_wl1flo);
    cudaGetSymbolAddress((void**)&wl1bhi, g_wl1bhi); cudaGetSymbolAddress((void**)&wl1blo, g_wl1blo);
    cudaGetSymbolAddress((void**)&o0hi,   g_o0hi);   cudaGetSymbolAddress((void**)&o0lo,   g_o0lo);
    cudaGetSymbolAddress((void**)&wh0fhi, g_whh0fhi); cudaGetSymbolAddress((void**)&wh0flo, g_whh0flo);
    cudaGetSymbolAddress((void**)&wh0bhi, g_whh0bhi); cudaGetSymbolAddress((void**)&wh0blo, g_whh0blo);
    cudaGetSymbolAddress((void**)&wh1fhi, g_whh1fhi); cudaGetSymbolAddress((void**)&wh1flo, g_whh1flo);
    cudaGetSymbolAddress((void**)&wh1bhi, g_whh1bhi); cudaGetSymbolAddress((void**)&wh1blo, g_whh1blo);

    cudaFuncSetAttribute(tc_gemm, cudaFuncAttributeMaxDynamicSharedMemorySize, GEMM_SMEM_BYTES);
    cudaFuncSetAttribute(lstm_rec_kernel, cudaFuncAttributeMaxDynamicSharedMemorySize, REC_SMEM);

    #define CONV(src, hi, lo, n) conv_split_kernel<<<((n) + 255) / 256, 256>>>(src, hi, lo, n)
    CONV(x, xhi, xlo, M_ROWS * 80);
    CONV(fe_w1, w1hi, w1lo, 1024 * 80);
    CONV(fe_w2, w2hi, w2lo, 2560 * 1024);
    CONV(w_ih_l0f, wl0fhi, wl0flo, 1024 * 2560);
    CONV(w_ih_l0b, wl0bhi, wl0blo, 1024 * 2560);
    CONV(w_ih_l1f, wl1fhi, wl1flo, 1024 * 512);
    CONV(w_ih_l1b, wl1bhi, wl1blo, 1024 * 512);
    CONV(w_hh_l0f, wh0fhi, wh0flo, 1024 * 256);
    CONV(w_hh_l0b, wh0bhi, wh0blo, 1024 * 256);
    CONV(w_hh_l1f, wh1fhi, wh1flo, 1024 * 256);
    CONV(w_hh_l1b, wh1bhi, wh1blo, 1024 * 256);

    // feature extractor
    tc_gemm<<<dim3(8,  M_ROWS / 128), 256, GEMM_SMEM_BYTES>>>(
        xhi, xlo, w1hi, w1lo, nullptr, nullptr,
        fe_b1, nullptr, nullptr, nullptr,
        h1, nullptr, h1hi, h1lo, M_ROWS, 1024, 80, 1, 8);
    tc_gemm<<<dim3(20, M_ROWS / 128), 256, GEMM_SMEM_BYTES>>>(
        h1hi, h1lo, w2hi, w2lo, nullptr, nullptr,
        fe_b2, nullptr, nullptr, nullptr,
        h2, nullptr, h2hi, h2lo, M_ROWS, 2560, 1024, 1, 20);

    // layer 0: MERGED f+b gate precompute (shared A = h2) + recurrence
    tc_gemm<<<dim3(16, M_ROWS / 128), 256, GEMM_SMEM_BYTES>>>(
        h2hi, h2lo, wl0fhi, wl0flo, wl0bhi, wl0blo,
        b_ih_l0f, b_hh_l0f, b_ih_l0b, b_hh_l0b,
        xgf, xgb, nullptr, nullptr, M_ROWS, 1024, 2560, 0, 8);
    init_rec_kernel<<<64, 256>>>();
    lstm_rec_kernel<<<2 * NBLK_R, 256, REC_SMEM>>>(
        xgf, xgb, wh0fhi, wh0flo, wh0bhi, wh0blo, o0);

    // layer 1: MERGED f+b gate precompute (shared A = o0 split)
    CONV(o0, o0hi, o0lo, M_ROWS * 512);
    tc_gemm<<<dim3(16, M_ROWS / 128), 256, GEMM_SMEM_BYTES>>>(
        o0hi, o0lo, wl1fhi, wl1flo, wl1bhi, wl1blo,
        b_ih_l1f, b_hh_l1f, b_ih_l1b, b_hh_l1b,
        xgf, xgb, nullptr, nullptr, M_ROWS, 1024, 512, 0, 8);
    init_rec_kernel<<<64, 256>>>();
    lstm_rec_kernel<<<2 * NBLK_R, 256, REC_SMEM>>>(
        xgf, xgb, wh1fhi, wh1flo, wh1bhi, wh1blo, o1);

    // classifier
    fc_kernel<<<M_ROWS / 8, 256>>>(o1, fc_w, fc_b, out);
    #undef CONV
}